// round 1
// baseline (speedup 1.0000x reference)
#include <cuda_runtime.h>
#include <math.h>

// Problem constants
#define CC   512
#define HWN  4096
#define BB   8
#define GG   32
#define CPG  16          // channels per group
#define EPSF 1e-6f
#define ALPHAF 0.044194173824159216f

// ---------------------------------------------------------------------------
// Device-global scratch (allocation-free workaround; ~832 MB total)
// ---------------------------------------------------------------------------
__device__ float g_h[BB * HWN * CC];    // normalized, transposed to [b][n][c]
__device__ float g_q[BB * HWN * CC];
__device__ float g_k[BB * HWN * CC];
__device__ float g_v[BB * HWN * CC];
__device__ float g_o[BB * HWN * CC];    // attention output [b][n][c]
__device__ float g_s[(size_t)BB * HWN * HWN];  // scores [b][n][m]  (512 MB)
__device__ float g_mu[BB * GG];
__device__ float g_rstd[BB * GG];

// ---------------------------------------------------------------------------
// GroupNorm statistics: one block per (b, g); reduce 16*4096 = 65536 elements
// ---------------------------------------------------------------------------
__global__ void gn_stats_kernel(const float* __restrict__ x) {
    const int bg = blockIdx.x;            // 0..255
    const int b  = bg / GG;
    const int g  = bg % GG;
    const float* xp = x + ((size_t)b * CC + (size_t)g * CPG) * HWN;

    float s = 0.f, ss = 0.f;
    for (int i = threadIdx.x; i < CPG * HWN; i += 256) {
        float v = xp[i];
        s  += v;
        ss += v * v;
    }
    __shared__ float sh1[256], sh2[256];
    sh1[threadIdx.x] = s;
    sh2[threadIdx.x] = ss;
    __syncthreads();
    for (int o = 128; o > 0; o >>= 1) {
        if (threadIdx.x < o) {
            sh1[threadIdx.x] += sh1[threadIdx.x + o];
            sh2[threadIdx.x] += sh2[threadIdx.x + o];
        }
        __syncthreads();
    }
    if (threadIdx.x == 0) {
        const float inv_n = 1.f / (CPG * HWN);
        float mu  = sh1[0] * inv_n;
        float var = sh2[0] * inv_n - mu * mu;
        g_mu[bg]   = mu;
        g_rstd[bg] = rsqrtf(var + EPSF);
    }
}

// ---------------------------------------------------------------------------
// Normalize + transpose: h[b][n][c] = (x[b][c][n]-mu)*rstd*gamma[c] + beta[c]
// 32x32 smem tile transpose, block (32,8), grid (HW/32, C/32, B)
// ---------------------------------------------------------------------------
__global__ void gn_norm_t_kernel(const float* __restrict__ x,
                                 const float* __restrict__ gamma,
                                 const float* __restrict__ beta) {
    __shared__ float tile[32][33];
    const int b  = blockIdx.z;
    const int n0 = blockIdx.x * 32;
    const int c0 = blockIdx.y * 32;

    #pragma unroll
    for (int i = 0; i < 4; i++) {
        int c = c0 + threadIdx.y + i * 8;
        int n = n0 + threadIdx.x;
        float v = x[((size_t)b * CC + c) * HWN + n];
        int gidx = b * GG + (c / CPG);
        v = (v - g_mu[gidx]) * g_rstd[gidx] * gamma[c] + beta[c];
        tile[threadIdx.y + i * 8][threadIdx.x] = v;
    }
    __syncthreads();
    #pragma unroll
    for (int i = 0; i < 4; i++) {
        int n = n0 + threadIdx.y + i * 8;
        int c = c0 + threadIdx.x;
        g_h[((size_t)b * HWN + n) * CC + c] = tile[threadIdx.x][threadIdx.y + i * 8];
    }
}

// ---------------------------------------------------------------------------
// Generic 128x128x8 fp32 SGEMM, 256 threads, 8x8 microtiles.
// MODE 0: C = A[M,K] * B[N,K]^T + bias[N]                    (QKV projections)
// MODE 1: C = alpha * A[M,K] * B[N,K]^T                      (scores, batched)
// MODE 2: C = A[M,K] * B[K,N]                                (attn @ V, batched)
// MODE 3: out[b][j][n] = A*Wo^T + bias[j] + resid[b][j][n]   (final proj + res,
//                                                             transposed store)
// ---------------------------------------------------------------------------
template <int MODE>
__global__ void __launch_bounds__(256, 2) gemm128_kernel(
    const float* __restrict__ A, const float* __restrict__ Bm,
    const float* __restrict__ bias, const float* __restrict__ resid,
    float* __restrict__ Cout,
    int M, int N, int K,
    size_t sA, size_t sB, size_t sC, float alpha)
{
    __shared__ float As[8][128];
    __shared__ float Bs[8][128];

    const int tid = threadIdx.x;
    const int m0 = blockIdx.y * 128;
    const int n0 = blockIdx.x * 128;

    A    += (size_t)blockIdx.z * sA;
    Bm   += (size_t)blockIdx.z * sB;
    Cout += (size_t)blockIdx.z * sC;

    const int lrow = tid >> 1;          // 0..127  (TN loaders)
    const int lk   = (tid & 1) * 4;     // 0 or 4
    const int bk   = tid >> 5;          // 0..7    (NN loader)
    const int bn   = (tid & 31) * 4;    // 0..124

    const int ty = tid >> 4;            // 0..15
    const int tx = tid & 15;            // 0..15

    float acc[8][8];
    #pragma unroll
    for (int i = 0; i < 8; i++)
        #pragma unroll
        for (int j = 0; j < 8; j++) acc[i][j] = 0.f;

    for (int k0 = 0; k0 < K; k0 += 8) {
        float4 av = *(const float4*)(A + (size_t)(m0 + lrow) * K + k0 + lk);
        float4 bv;
        if (MODE == 2) {
            bv = *(const float4*)(Bm + (size_t)(k0 + bk) * N + n0 + bn);
        } else {
            bv = *(const float4*)(Bm + (size_t)(n0 + lrow) * K + k0 + lk);
        }

        __syncthreads();   // previous iteration's consumers done
        As[lk + 0][lrow] = av.x;
        As[lk + 1][lrow] = av.y;
        As[lk + 2][lrow] = av.z;
        As[lk + 3][lrow] = av.w;
        if (MODE == 2) {
            *(float4*)&Bs[bk][bn] = bv;
        } else {
            Bs[lk + 0][lrow] = bv.x;
            Bs[lk + 1][lrow] = bv.y;
            Bs[lk + 2][lrow] = bv.z;
            Bs[lk + 3][lrow] = bv.w;
        }
        __syncthreads();

        #pragma unroll
        for (int kk = 0; kk < 8; kk++) {
            float a[8], b[8];
            #pragma unroll
            for (int i = 0; i < 8; i++) a[i] = As[kk][ty * 8 + i];
            #pragma unroll
            for (int j = 0; j < 8; j++) b[j] = Bs[kk][tx * 8 + j];
            #pragma unroll
            for (int i = 0; i < 8; i++)
                #pragma unroll
                for (int j = 0; j < 8; j++)
                    acc[i][j] += a[i] * b[j];
        }
    }

    // ---- epilogue ----
    if (MODE == 3) {
        #pragma unroll
        for (int i = 0; i < 8; i++) {
            int mrow = m0 + ty * 8 + i;
            int b = mrow >> 12;          // /4096
            int n = mrow & 4095;
            #pragma unroll
            for (int j = 0; j < 8; j++) {
                int jj = n0 + tx * 8 + j;
                size_t oi = ((size_t)b * CC + jj) * HWN + n;
                Cout[oi] = acc[i][j] + bias[jj] + resid[oi];
            }
        }
    } else {
        #pragma unroll
        for (int i = 0; i < 8; i++) {
            size_t r = (size_t)(m0 + ty * 8 + i) * N + n0 + tx * 8;
            float tmp[8];
            #pragma unroll
            for (int j = 0; j < 8; j++) {
                if (MODE == 0)      tmp[j] = acc[i][j] + bias[n0 + tx * 8 + j];
                else if (MODE == 1) tmp[j] = acc[i][j] * alpha;
                else                tmp[j] = acc[i][j];
            }
            *(float4*)(Cout + r)     = make_float4(tmp[0], tmp[1], tmp[2], tmp[3]);
            *(float4*)(Cout + r + 4) = make_float4(tmp[4], tmp[5], tmp[6], tmp[7]);
        }
    }
}

// ---------------------------------------------------------------------------
// Row softmax over 4096-wide rows; one block (256 thr) per row.
// ---------------------------------------------------------------------------
__global__ void softmax_rows_kernel(float* __restrict__ S) {
    const size_t row = blockIdx.x;
    float* p = S + row * HWN;
    const int tid = threadIdx.x;

    float vals[16];
    float mx = -1e30f;
    #pragma unroll
    for (int i = 0; i < 16; i++) {
        vals[i] = p[tid + i * 256];
        mx = fmaxf(mx, vals[i]);
    }
    __shared__ float sh[256];
    sh[tid] = mx;
    __syncthreads();
    for (int o = 128; o > 0; o >>= 1) {
        if (tid < o) sh[tid] = fmaxf(sh[tid], sh[tid + o]);
        __syncthreads();
    }
    const float rmax = sh[0];
    __syncthreads();

    float sum = 0.f;
    #pragma unroll
    for (int i = 0; i < 16; i++) {
        vals[i] = __expf(vals[i] - rmax);
        sum += vals[i];
    }
    sh[tid] = sum;
    __syncthreads();
    for (int o = 128; o > 0; o >>= 1) {
        if (tid < o) sh[tid] += sh[tid + o];
        __syncthreads();
    }
    const float inv = 1.f / sh[0];
    #pragma unroll
    for (int i = 0; i < 16; i++)
        p[tid + i * 256] = vals[i] * inv;
}

// ---------------------------------------------------------------------------
// Launch
// ---------------------------------------------------------------------------
extern "C" void kernel_launch(void* const* d_in, const int* in_sizes, int n_in,
                              void* d_out, int out_size) {
    const float* x     = (const float*)d_in[0];
    const float* gamma = (const float*)d_in[1];
    const float* beta  = (const float*)d_in[2];
    const float* wq    = (const float*)d_in[3];
    const float* bq    = (const float*)d_in[4];
    const float* wk    = (const float*)d_in[5];
    const float* bk    = (const float*)d_in[6];
    const float* wv    = (const float*)d_in[7];
    const float* bv    = (const float*)d_in[8];
    const float* wo    = (const float*)d_in[9];
    const float* bo    = (const float*)d_in[10];
    float* out = (float*)d_out;

    float *ph, *pq, *pk, *pv, *po, *ps;
    cudaGetSymbolAddress((void**)&ph, g_h);
    cudaGetSymbolAddress((void**)&pq, g_q);
    cudaGetSymbolAddress((void**)&pk, g_k);
    cudaGetSymbolAddress((void**)&pv, g_v);
    cudaGetSymbolAddress((void**)&po, g_o);
    cudaGetSymbolAddress((void**)&ps, g_s);

    // 1) GroupNorm stats
    gn_stats_kernel<<<BB * GG, 256>>>(x);

    // 2) Normalize + transpose -> h[b][n][c]
    gn_norm_t_kernel<<<dim3(HWN / 32, CC / 32, BB), dim3(32, 8)>>>(x, gamma, beta);

    // 3) Q, K, V projections: [32768,512] = h * W^T + b
    const int Mflat = BB * HWN;
    dim3 gproj(CC / 128, Mflat / 128);
    gemm128_kernel<0><<<gproj, 256>>>(ph, wq, bq, nullptr, pq,
                                      Mflat, CC, CC, 0, 0, 0, 1.f);
    gemm128_kernel<0><<<gproj, 256>>>(ph, wk, bk, nullptr, pk,
                                      Mflat, CC, CC, 0, 0, 0, 1.f);
    gemm128_kernel<0><<<gproj, 256>>>(ph, wv, bv, nullptr, pv,
                                      Mflat, CC, CC, 0, 0, 0, 1.f);

    // 4) Scores: S[b] = alpha * Q[b] K[b]^T   [4096 x 4096], batched over B
    dim3 gscore(HWN / 128, HWN / 128, BB);
    gemm128_kernel<1><<<gscore, 256>>>(pq, pk, nullptr, nullptr, ps,
                                       HWN, HWN, CC,
                                       (size_t)HWN * CC, (size_t)HWN * CC,
                                       (size_t)HWN * HWN, ALPHAF);

    // 5) Row softmax
    softmax_rows_kernel<<<BB * HWN, 256>>>(ps);

    // 6) O[b] = S[b] * V[b]   [4096 x 512], batched over B (NN gemm)
    dim3 gsv(CC / 128, HWN / 128, BB);
    gemm128_kernel<2><<<gsv, 256>>>(ps, pv, nullptr, nullptr, po,
                                    HWN, CC, HWN,
                                    (size_t)HWN * HWN, (size_t)HWN * CC,
                                    (size_t)HWN * CC, 1.f);

    // 7) Final projection + bias + residual, transposed store to [b][c][hw]
    gemm128_kernel<3><<<gproj, 256>>>(po, wo, bo, x, out,
                                      Mflat, CC, CC, 0, 0, 0, 1.f);
}

// round 3
// speedup vs baseline: 3.5048x; 3.5048x over previous
#include <cuda_runtime.h>
#include <cuda.h>
#include <math.h>
#include <stdint.h>

// Problem constants
#define CC   512
#define HWN  4096
#define BB   8
#define GG   32
#define CPG  16
#define EPSF 1e-6f
#define ALPHAF 0.044194173824159216f

// GEMM tiling
#define BM 128
#define BN 256
#define KC 32
#define STAGES 3
#define PITCH 36                       // floats; 36%32==4 -> conflict-free patterns
#define A_STG (BM * PITCH)             // 4608 floats
#define B_STG (BN * PITCH)             // 9216 floats
#define STG_FLOATS (A_STG + B_STG)     // 13824
#define STG_BYTES (STG_FLOATS * 4)     // 55296
#define SMEM_BYTES (STAGES * STG_BYTES)  // 165888
#define TR_PITCH 132                   // epilogue transpose pitch

// ---------------------------------------------------------------------------
// Device-global scratch
// ---------------------------------------------------------------------------
__device__ float g_h[BB * HWN * CC];           // normalized [b][n][c] (tf32-rounded)
__device__ float g_q[BB * HWN * CC];           // [b][n][c] (tf32)
__device__ float g_k[BB * HWN * CC];           // [b][n][c] (tf32)
__device__ float g_v[BB * HWN * CC];           // V transposed [b][c][n] (tf32)
__device__ float g_o[BB * HWN * CC];           // attn out [b][n][c] (tf32)
__device__ float g_s[(size_t)BB * HWN * HWN];  // scores / probs
__device__ float g_wr[4 * CC * CC];            // tf32-rounded weights (q,k,v,o)
__device__ float g_mu[BB * GG];
__device__ float g_rstd[BB * GG];

// ---------------------------------------------------------------------------
// Helpers
// ---------------------------------------------------------------------------
__device__ __forceinline__ uint32_t smem_u32(const void* p) {
    uint32_t a;
    asm("{ .reg .u64 t; cvta.to.shared.u64 t, %1; cvt.u32.u64 %0, t; }"
        : "=r"(a) : "l"(p));
    return a;
}
__device__ __forceinline__ uint32_t f2tf32(float x) {
    uint32_t u;
    asm("cvt.rna.tf32.f32 %0, %1;" : "=r"(u) : "f"(x));
    return u;
}
__device__ __forceinline__ float rnd_tf32(float x) {
    return __uint_as_float(f2tf32(x));
}
__device__ __forceinline__ void cp_async16(uint32_t dst, const void* src) {
    asm volatile("cp.async.cg.shared.global [%0], [%1], 16;" :: "r"(dst), "l"(src));
}
__device__ __forceinline__ void cp_commit() {
    asm volatile("cp.async.commit_group;");
}
__device__ __forceinline__ void mma_tf32(float* d, const uint32_t* a, const uint32_t* b) {
    asm volatile(
        "mma.sync.aligned.m16n8k8.row.col.f32.tf32.tf32.f32 "
        "{%0,%1,%2,%3},{%4,%5,%6,%7},{%8,%9},{%0,%1,%2,%3};"
        : "+f"(d[0]), "+f"(d[1]), "+f"(d[2]), "+f"(d[3])
        : "r"(a[0]), "r"(a[1]), "r"(a[2]), "r"(a[3]), "r"(b[0]), "r"(b[1]));
}

// ---------------------------------------------------------------------------
// tf32 tensor-core GEMM:  C[M,N] = A[M,K] * B[N,K]^T  (both K-major)
//  EPI 0: + bias[n], row-major store (RND optional)
//  EPI 1: * alpha,   row-major store (RND optional)
//  EPI 2: transposed store out[b][ch][tok] = acc + bias[ch]            (RND)
//  EPI 3: transposed store out[b][ch][tok] = acc + bias[ch] + resid
// ---------------------------------------------------------------------------
template <int EPI, int RND>
__global__ void __launch_bounds__(256, 1)
tgemm_kernel(const float* __restrict__ A, const float* __restrict__ Bm,
             const float* __restrict__ bias, const float* __restrict__ resid,
             float* __restrict__ Cout,
             int lda, int ldb, int ldc,
             size_t sA, size_t sB, size_t sC,
             int NC, float alpha)
{
    extern __shared__ float smem_f[];
    const uint32_t smem_base = smem_u32(smem_f);
    const int tid = threadIdx.x;
    const int wid = tid >> 5;
    const int lane = tid & 31;
    const int g = lane >> 2;       // groupID 0..7
    const int kin = lane & 3;      // thread-in-group 0..3
    const int wm = wid & 1;        // warp m index (2)
    const int wn = wid >> 1;       // warp n index (4)

    const int m0 = blockIdx.y * BM;
    const int n0 = blockIdx.x * BN;
    A    += (size_t)blockIdx.z * sA;
    Bm   += (size_t)blockIdx.z * sB;
    Cout += (size_t)blockIdx.z * sC;

    float acc[4][8][4];
    #pragma unroll
    for (int mt = 0; mt < 4; mt++)
        #pragma unroll
        for (int nt = 0; nt < 8; nt++)
            #pragma unroll
            for (int c = 0; c < 4; c++) acc[mt][nt][c] = 0.f;

    // ---- prefetch first STAGES-1 chunks ----
    #pragma unroll
    for (int s = 0; s < STAGES - 1; s++) {
        const int k0 = s * KC;
        const uint32_t sb = smem_base + s * STG_BYTES;
        #pragma unroll
        for (int i = 0; i < 4; i++) {
            int idx = i * 256 + tid;
            int row = idx >> 3, kq = idx & 7;
            cp_async16(sb + (row * PITCH + kq * 4) * 4,
                       A + (size_t)(m0 + row) * lda + k0 + kq * 4);
        }
        #pragma unroll
        for (int i = 0; i < 8; i++) {
            int idx = i * 256 + tid;
            int row = idx >> 3, kq = idx & 7;
            cp_async16(sb + A_STG * 4 + (row * PITCH + kq * 4) * 4,
                       Bm + (size_t)(n0 + row) * ldb + k0 + kq * 4);
        }
        cp_commit();
    }

    // ---- main loop ----
    for (int c = 0; c < NC; c++) {
        asm volatile("cp.async.wait_group %0;" :: "n"(STAGES - 2));
        __syncthreads();

        const int pf = c + STAGES - 1;
        if (pf < NC) {
            const int k0 = pf * KC;
            const uint32_t sb = smem_base + (pf % STAGES) * STG_BYTES;
            #pragma unroll
            for (int i = 0; i < 4; i++) {
                int idx = i * 256 + tid;
                int row = idx >> 3, kq = idx & 7;
                cp_async16(sb + (row * PITCH + kq * 4) * 4,
                           A + (size_t)(m0 + row) * lda + k0 + kq * 4);
            }
            #pragma unroll
            for (int i = 0; i < 8; i++) {
                int idx = i * 256 + tid;
                int row = idx >> 3, kq = idx & 7;
                cp_async16(sb + A_STG * 4 + (row * PITCH + kq * 4) * 4,
                           Bm + (size_t)(n0 + row) * ldb + k0 + kq * 4);
            }
            cp_commit();
        }

        const uint32_t* As = (const uint32_t*)(smem_f + (c % STAGES) * STG_FLOATS);
        const uint32_t* Bs = As + A_STG;

        #pragma unroll
        for (int ks = 0; ks < 4; ks++) {
            uint32_t af[4][4];
            #pragma unroll
            for (int mt = 0; mt < 4; mt++) {
                int base = (wm * 64 + mt * 16 + g) * PITCH + ks * 8 + kin;
                af[mt][0] = As[base];
                af[mt][1] = As[base + 8 * PITCH];
                af[mt][2] = As[base + 4];
                af[mt][3] = As[base + 8 * PITCH + 4];
            }
            uint32_t bf[8][2];
            #pragma unroll
            for (int nt = 0; nt < 8; nt++) {
                int base = (wn * 64 + nt * 8 + g) * PITCH + ks * 8 + kin;
                bf[nt][0] = Bs[base];
                bf[nt][1] = Bs[base + 4];
            }
            #pragma unroll
            for (int mt = 0; mt < 4; mt++)
                #pragma unroll
                for (int nt = 0; nt < 8; nt++)
                    mma_tf32(acc[mt][nt], af[mt], bf[nt]);
        }
    }

    // ---- epilogue ----
    if (EPI <= 1) {
        #pragma unroll
        for (int mt = 0; mt < 4; mt++) {
            int r0 = m0 + wm * 64 + mt * 16 + g;
            #pragma unroll
            for (int nt = 0; nt < 8; nt++) {
                int ch = n0 + wn * 64 + nt * 8 + kin * 2;
                float v0 = acc[mt][nt][0], v1 = acc[mt][nt][1];
                float v2 = acc[mt][nt][2], v3 = acc[mt][nt][3];
                if (EPI == 0) {
                    float b0 = bias[ch], b1 = bias[ch + 1];
                    v0 += b0; v1 += b1; v2 += b0; v3 += b1;
                } else {
                    v0 *= alpha; v1 *= alpha; v2 *= alpha; v3 *= alpha;
                }
                if (RND) {
                    v0 = rnd_tf32(v0); v1 = rnd_tf32(v1);
                    v2 = rnd_tf32(v2); v3 = rnd_tf32(v3);
                }
                *(float2*)(Cout + (size_t)r0 * ldc + ch)       = make_float2(v0, v1);
                *(float2*)(Cout + (size_t)(r0 + 8) * ldc + ch) = make_float2(v2, v3);
            }
        }
    } else {
        // transpose through smem: tr[ch][tok], 256 x 128
        __syncthreads();
        float* tr = smem_f;
        #pragma unroll
        for (int mt = 0; mt < 4; mt++) {
            int tok = wm * 64 + mt * 16 + g;
            #pragma unroll
            for (int nt = 0; nt < 8; nt++) {
                int ch = wn * 64 + nt * 8 + kin * 2;
                tr[(ch    ) * TR_PITCH + tok    ] = acc[mt][nt][0];
                tr[(ch + 1) * TR_PITCH + tok    ] = acc[mt][nt][1];
                tr[(ch    ) * TR_PITCH + tok + 8] = acc[mt][nt][2];
                tr[(ch + 1) * TR_PITCH + tok + 8] = acc[mt][nt][3];
            }
        }
        __syncthreads();
        const int bidx = m0 >> 12;
        const int tok0 = m0 & 4095;
        #pragma unroll 4
        for (int i = 0; i < 32; i++) {
            int idx = i * 256 + tid;
            int ch = idx >> 5, t4 = (idx & 31) * 4;
            float4 v = *(float4*)&tr[ch * TR_PITCH + t4];
            float bv = bias[n0 + ch];
            v.x += bv; v.y += bv; v.z += bv; v.w += bv;
            size_t oidx = ((size_t)bidx * CC + n0 + ch) * HWN + tok0 + t4;
            if (EPI == 3) {
                float4 rr = *(const float4*)(resid + oidx);
                v.x += rr.x; v.y += rr.y; v.z += rr.z; v.w += rr.w;
            }
            if (RND) {
                v.x = rnd_tf32(v.x); v.y = rnd_tf32(v.y);
                v.z = rnd_tf32(v.z); v.w = rnd_tf32(v.w);
            }
            *(float4*)(Cout + oidx) = v;
        }
    }
}

// ---------------------------------------------------------------------------
// Round weights to tf32 once
// ---------------------------------------------------------------------------
__global__ void round_w_kernel(const float* __restrict__ src, float* __restrict__ dst) {
    int i = (blockIdx.x * 256 + threadIdx.x) * 4;
    float4 v = *(const float4*)(src + i);
    v.x = rnd_tf32(v.x); v.y = rnd_tf32(v.y);
    v.z = rnd_tf32(v.z); v.w = rnd_tf32(v.w);
    *(float4*)(dst + i) = v;
}

// ---------------------------------------------------------------------------
// GroupNorm stats
// ---------------------------------------------------------------------------
__global__ void gn_stats_kernel(const float* __restrict__ x) {
    const int bg = blockIdx.x;
    const int b = bg / GG, g = bg % GG;
    const float* xp = x + ((size_t)b * CC + (size_t)g * CPG) * HWN;
    float s = 0.f, ss = 0.f;
    for (int i = threadIdx.x; i < CPG * HWN; i += 256) {
        float v = xp[i];
        s += v; ss += v * v;
    }
    __shared__ float sh1[256], sh2[256];
    sh1[threadIdx.x] = s; sh2[threadIdx.x] = ss;
    __syncthreads();
    for (int o = 128; o > 0; o >>= 1) {
        if (threadIdx.x < o) {
            sh1[threadIdx.x] += sh1[threadIdx.x + o];
            sh2[threadIdx.x] += sh2[threadIdx.x + o];
        }
        __syncthreads();
    }
    if (threadIdx.x == 0) {
        const float inv_n = 1.f / (CPG * HWN);
        float mu = sh1[0] * inv_n;
        float var = sh2[0] * inv_n - mu * mu;
        g_mu[bg] = mu;
        g_rstd[bg] = rsqrtf(var + EPSF);
    }
}

// ---------------------------------------------------------------------------
// Normalize + transpose -> h[b][n][c], tf32-rounded
// ---------------------------------------------------------------------------
__global__ void gn_norm_t_kernel(const float* __restrict__ x,
                                 const float* __restrict__ gamma,
                                 const float* __restrict__ beta) {
    __shared__ float tile[32][33];
    const int b = blockIdx.z;
    const int n0 = blockIdx.x * 32;
    const int c0 = blockIdx.y * 32;
    #pragma unroll
    for (int i = 0; i < 4; i++) {
        int c = c0 + threadIdx.y + i * 8;
        int n = n0 + threadIdx.x;
        float v = x[((size_t)b * CC + c) * HWN + n];
        int gidx = b * GG + (c / CPG);
        v = (v - g_mu[gidx]) * g_rstd[gidx] * gamma[c] + beta[c];
        tile[threadIdx.y + i * 8][threadIdx.x] = rnd_tf32(v);
    }
    __syncthreads();
    #pragma unroll
    for (int i = 0; i < 4; i++) {
        int n = n0 + threadIdx.y + i * 8;
        int c = c0 + threadIdx.x;
        g_h[((size_t)b * HWN + n) * CC + c] = tile[threadIdx.x][threadIdx.y + i * 8];
    }
}

// ---------------------------------------------------------------------------
// Row softmax (4096-wide), stores tf32-rounded probabilities
// ---------------------------------------------------------------------------
__global__ void softmax_rows_kernel(float* __restrict__ S) {
    const size_t row = blockIdx.x;
    float* p = S + row * HWN;
    const int tid = threadIdx.x;
    float vals[16];
    float mx = -1e30f;
    #pragma unroll
    for (int i = 0; i < 16; i++) {
        vals[i] = p[tid + i * 256];
        mx = fmaxf(mx, vals[i]);
    }
    __shared__ float sh[256];
    sh[tid] = mx;
    __syncthreads();
    for (int o = 128; o > 0; o >>= 1) {
        if (tid < o) sh[tid] = fmaxf(sh[tid], sh[tid + o]);
        __syncthreads();
    }
    const float rmax = sh[0];
    __syncthreads();
    float sum = 0.f;
    #pragma unroll
    for (int i = 0; i < 16; i++) {
        vals[i] = __expf(vals[i] - rmax);
        sum += vals[i];
    }
    sh[tid] = sum;
    __syncthreads();
    for (int o = 128; o > 0; o >>= 1) {
        if (tid < o) sh[tid] += sh[tid + o];
        __syncthreads();
    }
    const float inv = 1.f / sh[0];
    #pragma unroll
    for (int i = 0; i < 16; i++)
        p[tid + i * 256] = rnd_tf32(vals[i] * inv);
}

// ---------------------------------------------------------------------------
// Launch
// ---------------------------------------------------------------------------
extern "C" void kernel_launch(void* const* d_in, const int* in_sizes, int n_in,
                              void* d_out, int out_size) {
    const float* x     = (const float*)d_in[0];
    const float* gamma = (const float*)d_in[1];
    const float* beta  = (const float*)d_in[2];
    const float* wq    = (const float*)d_in[3];
    const float* bq    = (const float*)d_in[4];
    const float* wk    = (const float*)d_in[5];
    const float* bk    = (const float*)d_in[6];
    const float* wv    = (const float*)d_in[7];
    const float* bv    = (const float*)d_in[8];
    const float* wo    = (const float*)d_in[9];
    const float* bo    = (const float*)d_in[10];
    float* out = (float*)d_out;

    float *ph, *pq, *pk, *pv, *po, *ps, *pw;
    cudaGetSymbolAddress((void**)&ph, g_h);
    cudaGetSymbolAddress((void**)&pq, g_q);
    cudaGetSymbolAddress((void**)&pk, g_k);
    cudaGetSymbolAddress((void**)&pv, g_v);
    cudaGetSymbolAddress((void**)&po, g_o);
    cudaGetSymbolAddress((void**)&ps, g_s);
    cudaGetSymbolAddress((void**)&pw, g_wr);

    cudaFuncSetAttribute(tgemm_kernel<0,1>, cudaFuncAttributeMaxDynamicSharedMemorySize, SMEM_BYTES);
    cudaFuncSetAttribute(tgemm_kernel<1,0>, cudaFuncAttributeMaxDynamicSharedMemorySize, SMEM_BYTES);
    cudaFuncSetAttribute(tgemm_kernel<1,1>, cudaFuncAttributeMaxDynamicSharedMemorySize, SMEM_BYTES);
    cudaFuncSetAttribute(tgemm_kernel<2,1>, cudaFuncAttributeMaxDynamicSharedMemorySize, SMEM_BYTES);
    cudaFuncSetAttribute(tgemm_kernel<3,0>, cudaFuncAttributeMaxDynamicSharedMemorySize, SMEM_BYTES);

    // 0) round weights to tf32 (q, k, v, o)
    const int wblk = CC * CC / (256 * 4);  // 256
    round_w_kernel<<<wblk, 256>>>(wq, pw + 0 * CC * CC);
    round_w_kernel<<<wblk, 256>>>(wk, pw + 1 * CC * CC);
    round_w_kernel<<<wblk, 256>>>(wv, pw + 2 * CC * CC);
    round_w_kernel<<<wblk, 256>>>(wo, pw + 3 * CC * CC);

    // 1) GroupNorm
    gn_stats_kernel<<<BB * GG, 256>>>(x);
    gn_norm_t_kernel<<<dim3(HWN / 32, CC / 32, BB), dim3(32, 8)>>>(x, gamma, beta);

    const int Mflat = BB * HWN;
    dim3 gproj(CC / BN, Mflat / BM, 1);     // (2, 256)

    // 2) projections
    tgemm_kernel<0,1><<<gproj, 256, SMEM_BYTES>>>(ph, pw + 0 * CC * CC, bq, nullptr, pq,
        CC, CC, CC, 0, 0, 0, CC / KC, 1.f);
    tgemm_kernel<0,1><<<gproj, 256, SMEM_BYTES>>>(ph, pw + 1 * CC * CC, bk, nullptr, pk,
        CC, CC, CC, 0, 0, 0, CC / KC, 1.f);
    tgemm_kernel<2,1><<<gproj, 256, SMEM_BYTES>>>(ph, pw + 2 * CC * CC, bv, nullptr, pv,
        CC, CC, CC, 0, 0, 0, CC / KC, 1.f);

    // 3) scores: S[b] = alpha * Q[b] K[b]^T
    dim3 gscore(HWN / BN, HWN / BM, BB);    // (16, 32, 8)
    tgemm_kernel<1,0><<<gscore, 256, SMEM_BYTES>>>(pq, pk, nullptr, nullptr, ps,
        CC, CC, HWN,
        (size_t)HWN * CC, (size_t)HWN * CC, (size_t)HWN * HWN,
        CC / KC, ALPHAF);

    // 4) softmax
    softmax_rows_kernel<<<BB * HWN, 256>>>(ps);

    // 5) O[b] = P[b] @ V[b]  (B = vT, K-major)
    dim3 gsv(CC / BN, HWN / BM, BB);        // (2, 32, 8)
    tgemm_kernel<1,1><<<gsv, 256, SMEM_BYTES>>>(ps, pv, nullptr, nullptr, po,
        HWN, HWN, CC,
        (size_t)HWN * HWN, (size_t)CC * HWN, (size_t)HWN * CC,
        HWN / KC, 1.f);

    // 6) final projection + bias + residual, transposed -> [b][c][hw]
    tgemm_kernel<3,0><<<gproj, 256, SMEM_BYTES>>>(po, pw + 3 * CC * CC, bo, x, out,
        CC, CC, CC, 0, 0, 0, CC / KC, 1.f);
}

// round 4
// speedup vs baseline: 6.3958x; 1.8248x over previous
#include <cuda_runtime.h>
#include <cuda.h>
#include <cuda_bf16.h>
#include <math.h>
#include <stdint.h>

// Problem constants
#define CC   512
#define HWN  4096
#define BB   8
#define GG   32
#define CPG  16
#define EPSF 1e-6f
#define ALPHAF 0.044194173824159216f

// GEMM tiling (bf16)
#define BM 128
#define BN 256
#define KC 64                          // bf16 elements per K chunk
#define STAGES 3
#define PITCH32 36                     // b32 words per smem row (32 data + 4 pad)
#define PITCHB  144                    // bytes per smem row
#define A_STG32 (BM * PITCH32)         // 4608 b32
#define STG_BYTES ((BM + BN) * PITCHB) // 55296
#define SMEM_BYTES (STAGES * STG_BYTES)  // 165888
#define TRB_PITCH 136                  // bf16 transpose pitch (bf16 units)
#define TRF_PITCH 132                  // f32 transpose pitch (f32 units)

typedef __nv_bfloat16 bf16;
typedef __nv_bfloat162 bf162;

// ---------------------------------------------------------------------------
// Device-global scratch
// ---------------------------------------------------------------------------
__device__ bf16 g_h[BB * HWN * CC];            // normalized [b][n][c]
__device__ bf16 g_q[BB * HWN * CC];            // [b][n][c]
__device__ bf16 g_k[BB * HWN * CC];            // [b][n][c]
__device__ bf16 g_v[BB * HWN * CC];            // V transposed [b][c][n]
__device__ bf16 g_o[BB * HWN * CC];            // attn out [b][n][c]
__device__ bf16 g_s[(size_t)BB * HWN * HWN];   // scores / probs (256MB)
__device__ bf16 g_wr[4 * CC * CC];             // bf16 weights (q,k,v,o)
__device__ float g_mu[BB * GG];
__device__ float g_rstd[BB * GG];

// ---------------------------------------------------------------------------
// Helpers
// ---------------------------------------------------------------------------
__device__ __forceinline__ uint32_t smem_u32(const void* p) {
    uint32_t a;
    asm("{ .reg .u64 t; cvta.to.shared.u64 t, %1; cvt.u32.u64 %0, t; }"
        : "=r"(a) : "l"(p));
    return a;
}
__device__ __forceinline__ void cp_async16(uint32_t dst, const void* src) {
    asm volatile("cp.async.cg.shared.global [%0], [%1], 16;" :: "r"(dst), "l"(src));
}
__device__ __forceinline__ void cp_commit() {
    asm volatile("cp.async.commit_group;");
}
__device__ __forceinline__ void mma_bf16(float* d, const uint32_t* a, const uint32_t* b) {
    asm volatile(
        "mma.sync.aligned.m16n8k16.row.col.f32.bf16.bf16.f32 "
        "{%0,%1,%2,%3},{%4,%5,%6,%7},{%8,%9},{%0,%1,%2,%3};"
        : "+f"(d[0]), "+f"(d[1]), "+f"(d[2]), "+f"(d[3])
        : "r"(a[0]), "r"(a[1]), "r"(a[2]), "r"(a[3]), "r"(b[0]), "r"(b[1]));
}
__device__ __forceinline__ void unpack2(uint32_t w, float& x, float& y) {
    bf162 h = *reinterpret_cast<bf162*>(&w);
    float2 f = __bfloat1622float2(h);
    x = f.x; y = f.y;
}
__device__ __forceinline__ uint32_t pack2(float x, float y) {
    bf162 h = __floats2bfloat162_rn(x, y);
    return *reinterpret_cast<uint32_t*>(&h);
}

// ---------------------------------------------------------------------------
// bf16 tensor-core GEMM:  C[M,N] = A[M,K] * B[N,K]^T  (both K-major bf16)
//  EPI 0: + bias[n], bf16 row-major store
//  EPI 1: * alpha,   bf16 row-major store
//  EPI 2: transposed bf16 store out[b][ch][tok] = acc + bias[ch]   (V proj)
//  EPI 3: transposed f32 store  out[b][ch][tok] = acc + bias + resid (final)
// ---------------------------------------------------------------------------
template <int EPI>
__global__ void __launch_bounds__(256, 1)
tgemm_kernel(const bf16* __restrict__ A, const bf16* __restrict__ Bm,
             const float* __restrict__ bias, const float* __restrict__ resid,
             void* __restrict__ Cout_,
             int lda, int ldb, int ldc,
             size_t sA, size_t sB, size_t sC,
             int NC, float alpha)
{
    extern __shared__ char smem[];
    const uint32_t smem_base = smem_u32(smem);
    const int tid = threadIdx.x;
    const int wid = tid >> 5;
    const int lane = tid & 31;
    const int g = lane >> 2;       // groupID 0..7
    const int kin = lane & 3;      // thread-in-group 0..3
    const int wm = wid & 1;        // warp m index (2)
    const int wn = wid >> 1;       // warp n index (4)

    const int m0 = blockIdx.y * BM;
    const int n0 = blockIdx.x * BN;
    A  += (size_t)blockIdx.z * sA;
    Bm += (size_t)blockIdx.z * sB;

    float acc[4][8][4];
    #pragma unroll
    for (int mt = 0; mt < 4; mt++)
        #pragma unroll
        for (int nt = 0; nt < 8; nt++)
            #pragma unroll
            for (int c = 0; c < 4; c++) acc[mt][nt][c] = 0.f;

    // ---- prefetch first STAGES-1 chunks ----
    #pragma unroll
    for (int s = 0; s < STAGES - 1; s++) {
        const int k0 = s * KC;
        const uint32_t sb = smem_base + s * STG_BYTES;
        #pragma unroll
        for (int i = 0; i < 4; i++) {
            int idx = i * 256 + tid;
            int row = idx >> 3, kq = idx & 7;
            cp_async16(sb + row * PITCHB + kq * 16,
                       A + (size_t)(m0 + row) * lda + k0 + kq * 8);
        }
        #pragma unroll
        for (int i = 0; i < 8; i++) {
            int idx = i * 256 + tid;
            int row = idx >> 3, kq = idx & 7;
            cp_async16(sb + BM * PITCHB + row * PITCHB + kq * 16,
                       Bm + (size_t)(n0 + row) * ldb + k0 + kq * 8);
        }
        cp_commit();
    }

    // ---- main loop ----
    for (int c = 0; c < NC; c++) {
        asm volatile("cp.async.wait_group %0;" :: "n"(STAGES - 2));
        __syncthreads();

        const int pf = c + STAGES - 1;
        if (pf < NC) {
            const int k0 = pf * KC;
            const uint32_t sb = smem_base + (pf % STAGES) * STG_BYTES;
            #pragma unroll
            for (int i = 0; i < 4; i++) {
                int idx = i * 256 + tid;
                int row = idx >> 3, kq = idx & 7;
                cp_async16(sb + row * PITCHB + kq * 16,
                           A + (size_t)(m0 + row) * lda + k0 + kq * 8);
            }
            #pragma unroll
            for (int i = 0; i < 8; i++) {
                int idx = i * 256 + tid;
                int row = idx >> 3, kq = idx & 7;
                cp_async16(sb + BM * PITCHB + row * PITCHB + kq * 16,
                           Bm + (size_t)(n0 + row) * ldb + k0 + kq * 8);
            }
            cp_commit();
        }

        const uint32_t* As = (const uint32_t*)(smem + (c % STAGES) * STG_BYTES);
        const uint32_t* Bs = As + A_STG32;

        #pragma unroll
        for (int ks = 0; ks < 4; ks++) {           // 4 x k16 per KC=64
            uint32_t af[4][4];
            #pragma unroll
            for (int mt = 0; mt < 4; mt++) {
                int base = (wm * 64 + mt * 16 + g) * PITCH32 + ks * 8 + kin;
                af[mt][0] = As[base];
                af[mt][1] = As[base + 8 * PITCH32];
                af[mt][2] = As[base + 4];
                af[mt][3] = As[base + 8 * PITCH32 + 4];
            }
            uint32_t bf[8][2];
            #pragma unroll
            for (int nt = 0; nt < 8; nt++) {
                int base = (wn * 64 + nt * 8 + g) * PITCH32 + ks * 8 + kin;
                bf[nt][0] = Bs[base];
                bf[nt][1] = Bs[base + 4];
            }
            #pragma unroll
            for (int mt = 0; mt < 4; mt++)
                #pragma unroll
                for (int nt = 0; nt < 8; nt++)
                    mma_bf16(acc[mt][nt], af[mt], bf[nt]);
        }
    }

    // ---- epilogue ----
    if (EPI <= 1) {
        bf16* Cout = (bf16*)Cout_ + (size_t)blockIdx.z * sC;
        #pragma unroll
        for (int mt = 0; mt < 4; mt++) {
            int r0 = m0 + wm * 64 + mt * 16 + g;
            #pragma unroll
            for (int nt = 0; nt < 8; nt++) {
                int ch = n0 + wn * 64 + nt * 8 + kin * 2;
                float v0 = acc[mt][nt][0], v1 = acc[mt][nt][1];
                float v2 = acc[mt][nt][2], v3 = acc[mt][nt][3];
                if (EPI == 0) {
                    float b0 = bias[ch], b1 = bias[ch + 1];
                    v0 += b0; v1 += b1; v2 += b0; v3 += b1;
                } else {
                    v0 *= alpha; v1 *= alpha; v2 *= alpha; v3 *= alpha;
                }
                *(bf162*)(Cout + (size_t)r0 * ldc + ch) = __floats2bfloat162_rn(v0, v1);
                *(bf162*)(Cout + (size_t)(r0 + 8) * ldc + ch) = __floats2bfloat162_rn(v2, v3);
            }
        }
    } else if (EPI == 2) {
        // bf16 transposed store via smem: tr[ch][tok], 256 x 128
        bf16* Cout = (bf16*)Cout_ + (size_t)blockIdx.z * sC;
        __syncthreads();
        bf16* tr = (bf16*)smem;
        #pragma unroll
        for (int mt = 0; mt < 4; mt++) {
            int tok = wm * 64 + mt * 16 + g;
            #pragma unroll
            for (int nt = 0; nt < 8; nt++) {
                int ch = wn * 64 + nt * 8 + kin * 2;
                float bv0 = bias[n0 + ch], bv1 = bias[n0 + ch + 1];
                tr[(ch    ) * TRB_PITCH + tok    ] = __float2bfloat16_rn(acc[mt][nt][0] + bv0);
                tr[(ch + 1) * TRB_PITCH + tok    ] = __float2bfloat16_rn(acc[mt][nt][1] + bv1);
                tr[(ch    ) * TRB_PITCH + tok + 8] = __float2bfloat16_rn(acc[mt][nt][2] + bv0);
                tr[(ch + 1) * TRB_PITCH + tok + 8] = __float2bfloat16_rn(acc[mt][nt][3] + bv1);
            }
        }
        __syncthreads();
        const int bidx = m0 >> 12;
        const int tok0 = m0 & 4095;
        // 256 ch x 128 tok bf16 -> 4096 uint4; 16 per thread
        #pragma unroll 4
        for (int i = 0; i < 16; i++) {
            int idx = i * 256 + tid;
            int ch = idx >> 4, t8 = (idx & 15) * 8;
            uint4 v = *(uint4*)&tr[ch * TRB_PITCH + t8];
            *(uint4*)(Cout + ((size_t)bidx * CC + n0 + ch) * HWN + tok0 + t8) = v;
        }
    } else {
        // f32 transposed store + bias + residual
        float* Cout = (float*)Cout_ + (size_t)blockIdx.z * sC;
        __syncthreads();
        float* tr = (float*)smem;
        #pragma unroll
        for (int mt = 0; mt < 4; mt++) {
            int tok = wm * 64 + mt * 16 + g;
            #pragma unroll
            for (int nt = 0; nt < 8; nt++) {
                int ch = wn * 64 + nt * 8 + kin * 2;
                tr[(ch    ) * TRF_PITCH + tok    ] = acc[mt][nt][0];
                tr[(ch + 1) * TRF_PITCH + tok    ] = acc[mt][nt][1];
                tr[(ch    ) * TRF_PITCH + tok + 8] = acc[mt][nt][2];
                tr[(ch + 1) * TRF_PITCH + tok + 8] = acc[mt][nt][3];
            }
        }
        __syncthreads();
        const int bidx = m0 >> 12;
        const int tok0 = m0 & 4095;
        #pragma unroll 4
        for (int i = 0; i < 32; i++) {
            int idx = i * 256 + tid;
            int ch = idx >> 5, t4 = (idx & 31) * 4;
            float4 v = *(float4*)&tr[ch * TRF_PITCH + t4];
            float bv = bias[n0 + ch];
            v.x += bv; v.y += bv; v.z += bv; v.w += bv;
            size_t oidx = ((size_t)bidx * CC + n0 + ch) * HWN + tok0 + t4;
            float4 rr = *(const float4*)(resid + oidx);
            v.x += rr.x; v.y += rr.y; v.z += rr.z; v.w += rr.w;
            *(float4*)(Cout + oidx) = v;
        }
    }
}

// ---------------------------------------------------------------------------
// Round weights to bf16 once
// ---------------------------------------------------------------------------
__global__ void round_w_kernel(const float* __restrict__ src, bf16* __restrict__ dst) {
    int i = (blockIdx.x * 256 + threadIdx.x) * 4;
    float4 v = *(const float4*)(src + i);
    uint2 o;
    o.x = pack2(v.x, v.y);
    o.y = pack2(v.z, v.w);
    *(uint2*)(dst + i) = o;
}

// ---------------------------------------------------------------------------
// GroupNorm stats
// ---------------------------------------------------------------------------
__global__ void gn_stats_kernel(const float* __restrict__ x) {
    const int bg = blockIdx.x;
    const int b = bg / GG, g = bg % GG;
    const float* xp = x + ((size_t)b * CC + (size_t)g * CPG) * HWN;
    float s = 0.f, ss = 0.f;
    for (int i = threadIdx.x; i < CPG * HWN; i += 256) {
        float v = xp[i];
        s += v; ss += v * v;
    }
    __shared__ float sh1[256], sh2[256];
    sh1[threadIdx.x] = s; sh2[threadIdx.x] = ss;
    __syncthreads();
    for (int o = 128; o > 0; o >>= 1) {
        if (threadIdx.x < o) {
            sh1[threadIdx.x] += sh1[threadIdx.x + o];
            sh2[threadIdx.x] += sh2[threadIdx.x + o];
        }
        __syncthreads();
    }
    if (threadIdx.x == 0) {
        const float inv_n = 1.f / (CPG * HWN);
        float mu = sh1[0] * inv_n;
        float var = sh2[0] * inv_n - mu * mu;
        g_mu[bg] = mu;
        g_rstd[bg] = rsqrtf(var + EPSF);
    }
}

// ---------------------------------------------------------------------------
// Normalize + transpose -> h[b][n][c] bf16
// ---------------------------------------------------------------------------
__global__ void gn_norm_t_kernel(const float* __restrict__ x,
                                 const float* __restrict__ gamma,
                                 const float* __restrict__ beta) {
    __shared__ float tile[32][33];
    const int b = blockIdx.z;
    const int n0 = blockIdx.x * 32;
    const int c0 = blockIdx.y * 32;
    #pragma unroll
    for (int i = 0; i < 4; i++) {
        int c = c0 + threadIdx.y + i * 8;
        int n = n0 + threadIdx.x;
        float v = x[((size_t)b * CC + c) * HWN + n];
        int gidx = b * GG + (c / CPG);
        v = (v - g_mu[gidx]) * g_rstd[gidx] * gamma[c] + beta[c];
        tile[threadIdx.y + i * 8][threadIdx.x] = v;
    }
    __syncthreads();
    #pragma unroll
    for (int i = 0; i < 4; i++) {
        int n = n0 + threadIdx.y + i * 8;
        int c = c0 + threadIdx.x;
        g_h[((size_t)b * HWN + n) * CC + c] =
            __float2bfloat16_rn(tile[threadIdx.x][threadIdx.y + i * 8]);
    }
}

// ---------------------------------------------------------------------------
// Row softmax over 4096-wide bf16 rows (f32 internal)
// ---------------------------------------------------------------------------
__global__ void softmax_rows_kernel(bf16* __restrict__ S) {
    const size_t row = blockIdx.x;
    bf16* p = S + row * HWN;
    const int tid = threadIdx.x;

    uint4 u0 = ((const uint4*)p)[tid];
    uint4 u1 = ((const uint4*)p)[tid + 256];
    float vals[16];
    unpack2(u0.x, vals[0], vals[1]);  unpack2(u0.y, vals[2], vals[3]);
    unpack2(u0.z, vals[4], vals[5]);  unpack2(u0.w, vals[6], vals[7]);
    unpack2(u1.x, vals[8], vals[9]);  unpack2(u1.y, vals[10], vals[11]);
    unpack2(u1.z, vals[12], vals[13]); unpack2(u1.w, vals[14], vals[15]);

    float mx = -1e30f;
    #pragma unroll
    for (int i = 0; i < 16; i++) mx = fmaxf(mx, vals[i]);
    __shared__ float sh[256];
    sh[tid] = mx;
    __syncthreads();
    for (int o = 128; o > 0; o >>= 1) {
        if (tid < o) sh[tid] = fmaxf(sh[tid], sh[tid + o]);
        __syncthreads();
    }
    const float rmax = sh[0];
    __syncthreads();
    float sum = 0.f;
    #pragma unroll
    for (int i = 0; i < 16; i++) {
        vals[i] = __expf(vals[i] - rmax);
        sum += vals[i];
    }
    sh[tid] = sum;
    __syncthreads();
    for (int o = 128; o > 0; o >>= 1) {
        if (tid < o) sh[tid] += sh[tid + o];
        __syncthreads();
    }
    const float inv = 1.f / sh[0];
    #pragma unroll
    for (int i = 0; i < 16; i++) vals[i] *= inv;

    u0.x = pack2(vals[0], vals[1]);   u0.y = pack2(vals[2], vals[3]);
    u0.z = pack2(vals[4], vals[5]);   u0.w = pack2(vals[6], vals[7]);
    u1.x = pack2(vals[8], vals[9]);   u1.y = pack2(vals[10], vals[11]);
    u1.z = pack2(vals[12], vals[13]); u1.w = pack2(vals[14], vals[15]);
    ((uint4*)p)[tid] = u0;
    ((uint4*)p)[tid + 256] = u1;
}

// ---------------------------------------------------------------------------
// Launch
// ---------------------------------------------------------------------------
extern "C" void kernel_launch(void* const* d_in, const int* in_sizes, int n_in,
                              void* d_out, int out_size) {
    const float* x     = (const float*)d_in[0];
    const float* gamma = (const float*)d_in[1];
    const float* beta  = (const float*)d_in[2];
    const float* wq    = (const float*)d_in[3];
    const float* bq    = (const float*)d_in[4];
    const float* wk    = (const float*)d_in[5];
    const float* bk    = (const float*)d_in[6];
    const float* wv    = (const float*)d_in[7];
    const float* bv    = (const float*)d_in[8];
    const float* wo    = (const float*)d_in[9];
    const float* bo    = (const float*)d_in[10];
    float* out = (float*)d_out;

    bf16 *ph, *pq, *pk, *pv, *po, *ps, *pw;
    cudaGetSymbolAddress((void**)&ph, g_h);
    cudaGetSymbolAddress((void**)&pq, g_q);
    cudaGetSymbolAddress((void**)&pk, g_k);
    cudaGetSymbolAddress((void**)&pv, g_v);
    cudaGetSymbolAddress((void**)&po, g_o);
    cudaGetSymbolAddress((void**)&ps, g_s);
    cudaGetSymbolAddress((void**)&pw, g_wr);

    cudaFuncSetAttribute(tgemm_kernel<0>, cudaFuncAttributeMaxDynamicSharedMemorySize, SMEM_BYTES);
    cudaFuncSetAttribute(tgemm_kernel<1>, cudaFuncAttributeMaxDynamicSharedMemorySize, SMEM_BYTES);
    cudaFuncSetAttribute(tgemm_kernel<2>, cudaFuncAttributeMaxDynamicSharedMemorySize, SMEM_BYTES);
    cudaFuncSetAttribute(tgemm_kernel<3>, cudaFuncAttributeMaxDynamicSharedMemorySize, SMEM_BYTES);

    // 0) weights -> bf16
    const int wblk = CC * CC / (256 * 4);  // 256
    round_w_kernel<<<wblk, 256>>>(wq, pw + 0 * CC * CC);
    round_w_kernel<<<wblk, 256>>>(wk, pw + 1 * CC * CC);
    round_w_kernel<<<wblk, 256>>>(wv, pw + 2 * CC * CC);
    round_w_kernel<<<wblk, 256>>>(wo, pw + 3 * CC * CC);

    // 1) GroupNorm
    gn_stats_kernel<<<BB * GG, 256>>>(x);
    gn_norm_t_kernel<<<dim3(HWN / 32, CC / 32, BB), dim3(32, 8)>>>(x, gamma, beta);

    const int Mflat = BB * HWN;
    dim3 gproj(CC / BN, Mflat / BM, 1);     // (2, 256)

    // 2) projections (q,k row-major; v transposed)
    tgemm_kernel<0><<<gproj, 256, SMEM_BYTES>>>(ph, pw + 0 * CC * CC, bq, nullptr, pq,
        CC, CC, CC, 0, 0, 0, CC / KC, 1.f);
    tgemm_kernel<0><<<gproj, 256, SMEM_BYTES>>>(ph, pw + 1 * CC * CC, bk, nullptr, pk,
        CC, CC, CC, 0, 0, 0, CC / KC, 1.f);
    tgemm_kernel<2><<<gproj, 256, SMEM_BYTES>>>(ph, pw + 2 * CC * CC, bv, nullptr, pv,
        CC, CC, CC, 0, 0, 0, CC / KC, 1.f);

    // 3) scores: S[b] = alpha * Q[b] K[b]^T  (bf16 out)
    dim3 gscore(HWN / BN, HWN / BM, BB);    // (16, 32, 8)
    tgemm_kernel<1><<<gscore, 256, SMEM_BYTES>>>(pq, pk, nullptr, nullptr, ps,
        CC, CC, HWN,
        (size_t)HWN * CC, (size_t)HWN * CC, (size_t)HWN * HWN,
        CC / KC, ALPHAF);

    // 4) softmax (bf16 in/out)
    softmax_rows_kernel<<<BB * HWN, 256>>>(ps);

    // 5) O[b] = P[b] @ V[b]  (B = vT, K-major), bf16 out
    dim3 gsv(CC / BN, HWN / BM, BB);        // (2, 32, 8)
    tgemm_kernel<1><<<gsv, 256, SMEM_BYTES>>>(ps, pv, nullptr, nullptr, po,
        HWN, HWN, CC,
        (size_t)HWN * HWN, (size_t)CC * HWN, (size_t)HWN * CC,
        HWN / KC, 1.f);

    // 6) final projection + bias + residual, transposed -> [b][c][hw] f32
    tgemm_kernel<3><<<gproj, 256, SMEM_BYTES>>>(po, pw + 3 * CC * CC, bo, x, out,
        CC, CC, CC, 0, 0, 0, CC / KC, 1.f);
}

// round 5
// speedup vs baseline: 6.6185x; 1.0348x over previous
#include <cuda_runtime.h>
#include <cuda.h>
#include <cuda_bf16.h>
#include <math.h>
#include <stdint.h>

// Problem constants
#define CC   512
#define HWN  4096
#define BB   8
#define GG   32
#define CPG  16
#define EPSF 1e-6f
#define ALPHAF 0.044194173824159216f

// GEMM tiling (bf16)
#define BM 128
#define BN 256
#define KC 64                          // bf16 elements per K chunk
#define STAGES 3
#define PITCH32 36                     // b32 words per smem row (32 data + 4 pad)
#define PITCHB  144                    // bytes per smem row
#define STG_BYTES ((BM + BN) * PITCHB) // 55296
#define SMEM_BYTES (STAGES * STG_BYTES)  // 165888
#define TRB_PITCH 136                  // bf16 transpose pitch (bf16 units)
#define TRF_PITCH 132                  // f32 transpose pitch (f32 units)

#define REG_SZ (BB * HWN * CC)         // 16M elements per q/k/v region

typedef __nv_bfloat16 bf16;
typedef __nv_bfloat162 bf162;

// ---------------------------------------------------------------------------
// Device-global scratch
// ---------------------------------------------------------------------------
__device__ bf16 g_h[BB * HWN * CC];            // normalized [b][n][c]
__device__ bf16 g_qkv[3 * REG_SZ];             // q rowmaj | k rowmaj | vT [b][c][n]
__device__ bf16 g_o[BB * HWN * CC];            // attn out [b][n][c]
__device__ bf16 g_s[(size_t)BB * HWN * HWN];   // scores / probs (256MB)
__device__ bf16 g_w[4 * CC * CC];              // packed weights: wq|wk|wv|wo rows
__device__ float g_bqkv[3 * CC];               // packed biases bq|bk|bv
__device__ float g_mu[BB * GG];
__device__ float g_rstd[BB * GG];

// ---------------------------------------------------------------------------
// Helpers
// ---------------------------------------------------------------------------
__device__ __forceinline__ uint32_t smem_u32(const void* p) {
    uint32_t a;
    asm("{ .reg .u64 t; cvta.to.shared.u64 t, %1; cvt.u32.u64 %0, t; }"
        : "=r"(a) : "l"(p));
    return a;
}
__device__ __forceinline__ void cp_async16(uint32_t dst, const void* src) {
    asm volatile("cp.async.cg.shared.global [%0], [%1], 16;" :: "r"(dst), "l"(src));
}
__device__ __forceinline__ void cp_commit() {
    asm volatile("cp.async.commit_group;");
}
__device__ __forceinline__ void mma_bf16(float* d, const uint32_t* a, const uint32_t* b) {
    asm volatile(
        "mma.sync.aligned.m16n8k16.row.col.f32.bf16.bf16.f32 "
        "{%0,%1,%2,%3},{%4,%5,%6,%7},{%8,%9},{%0,%1,%2,%3};"
        : "+f"(d[0]), "+f"(d[1]), "+f"(d[2]), "+f"(d[3])
        : "r"(a[0]), "r"(a[1]), "r"(a[2]), "r"(a[3]), "r"(b[0]), "r"(b[1]));
}
#define LDSM4(r0, r1, r2, r3, addr) \
    asm volatile("ldmatrix.sync.aligned.m8n8.x4.shared.b16 {%0,%1,%2,%3}, [%4];" \
        : "=r"(r0), "=r"(r1), "=r"(r2), "=r"(r3) : "r"(addr))

__device__ __forceinline__ void unpack2(uint32_t w, float& x, float& y) {
    bf162 h = *reinterpret_cast<bf162*>(&w);
    float2 f = __bfloat1622float2(h);
    x = f.x; y = f.y;
}
__device__ __forceinline__ uint32_t pack2(float x, float y) {
    bf162 h = __floats2bfloat162_rn(x, y);
    return *reinterpret_cast<uint32_t*>(&h);
}

// ---------------------------------------------------------------------------
// bf16 tensor-core GEMM:  C[M,N] = A[M,K] * B[N,K]^T  (both K-major bf16)
//  EPI 1: * alpha, bf16 row-major store (scores, SV)
//  EPI 3: transposed f32 store out[b][ch][tok] = acc + bias + resid (final)
//  EPI 4: fused QKV epilogue (q/k row-major, v transposed; device symbols)
// ---------------------------------------------------------------------------
template <int EPI>
__global__ void __launch_bounds__(256, 1)
tgemm_kernel(const bf16* __restrict__ A, const bf16* __restrict__ Bm,
             const float* __restrict__ bias, const float* __restrict__ resid,
             void* __restrict__ Cout_,
             int lda, int ldb, int ldc,
             size_t sA, size_t sB, size_t sC,
             int NC, float alpha)
{
    extern __shared__ char smem[];
    const uint32_t smem_base = smem_u32(smem);
    const int tid = threadIdx.x;
    const int wid = tid >> 5;
    const int lane = tid & 31;
    const int g = lane >> 2;       // groupID 0..7
    const int kin = lane & 3;      // thread-in-group 0..3
    const int wm = wid & 1;        // warp m index (2)
    const int wn = wid >> 1;       // warp n index (4)

    const int m0 = blockIdx.y * BM;
    const int n0 = blockIdx.x * BN;
    A  += (size_t)blockIdx.z * sA;
    Bm += (size_t)blockIdx.z * sB;

    // ldmatrix per-thread byte offsets (within a stage)
    const int lq = lane >> 3;      // 0..3 quadrant selector
    const int lr = lane & 7;       // row within matrix
    uint32_t aoff[4], boff[4];
    #pragma unroll
    for (int mt = 0; mt < 4; mt++)
        aoff[mt] = (uint32_t)((wm * 64 + mt * 16 + (lq & 1) * 8 + lr) * PITCHB
                              + (lq >> 1) * 16);
    #pragma unroll
    for (int p = 0; p < 4; p++)
        boff[p] = (uint32_t)(BM * PITCHB
                             + (wn * 64 + (2 * p + (lq >> 1)) * 8 + lr) * PITCHB
                             + (lq & 1) * 16);

    float acc[4][8][4];
    #pragma unroll
    for (int mt = 0; mt < 4; mt++)
        #pragma unroll
        for (int nt = 0; nt < 8; nt++)
            #pragma unroll
            for (int c = 0; c < 4; c++) acc[mt][nt][c] = 0.f;

    // ---- prefetch first STAGES-1 chunks ----
    #pragma unroll
    for (int s = 0; s < STAGES - 1; s++) {
        const int k0 = s * KC;
        const uint32_t sb = smem_base + s * STG_BYTES;
        #pragma unroll
        for (int i = 0; i < 4; i++) {
            int idx = i * 256 + tid;
            int row = idx >> 3, kq = idx & 7;
            cp_async16(sb + row * PITCHB + kq * 16,
                       A + (size_t)(m0 + row) * lda + k0 + kq * 8);
        }
        #pragma unroll
        for (int i = 0; i < 8; i++) {
            int idx = i * 256 + tid;
            int row = idx >> 3, kq = idx & 7;
            cp_async16(sb + BM * PITCHB + row * PITCHB + kq * 16,
                       Bm + (size_t)(n0 + row) * ldb + k0 + kq * 8);
        }
        cp_commit();
    }

    // ---- main loop ----
    for (int c = 0; c < NC; c++) {
        asm volatile("cp.async.wait_group %0;" :: "n"(STAGES - 2));
        __syncthreads();

        const int pf = c + STAGES - 1;
        if (pf < NC) {
            const int k0 = pf * KC;
            const uint32_t sb = smem_base + (pf % STAGES) * STG_BYTES;
            #pragma unroll
            for (int i = 0; i < 4; i++) {
                int idx = i * 256 + tid;
                int row = idx >> 3, kq = idx & 7;
                cp_async16(sb + row * PITCHB + kq * 16,
                           A + (size_t)(m0 + row) * lda + k0 + kq * 8);
            }
            #pragma unroll
            for (int i = 0; i < 8; i++) {
                int idx = i * 256 + tid;
                int row = idx >> 3, kq = idx & 7;
                cp_async16(sb + BM * PITCHB + row * PITCHB + kq * 16,
                           Bm + (size_t)(n0 + row) * ldb + k0 + kq * 8);
            }
            cp_commit();
        }

        const uint32_t sb = smem_base + (c % STAGES) * STG_BYTES;
        #pragma unroll
        for (int ks = 0; ks < 4; ks++) {           // 4 x k16 per KC=64
            const uint32_t kb = sb + ks * 32;
            uint32_t af[4][4];
            #pragma unroll
            for (int mt = 0; mt < 4; mt++)
                LDSM4(af[mt][0], af[mt][1], af[mt][2], af[mt][3], kb + aoff[mt]);
            uint32_t bf[8][2];
            #pragma unroll
            for (int p = 0; p < 4; p++)
                LDSM4(bf[2 * p][0], bf[2 * p][1], bf[2 * p + 1][0], bf[2 * p + 1][1],
                      kb + boff[p]);
            #pragma unroll
            for (int mt = 0; mt < 4; mt++)
                #pragma unroll
                for (int nt = 0; nt < 8; nt++)
                    mma_bf16(acc[mt][nt], af[mt], bf[nt]);
        }
    }

    // ---- epilogue ----
    if (EPI == 1) {
        bf16* Cout = (bf16*)Cout_ + (size_t)blockIdx.z * sC;
        #pragma unroll
        for (int mt = 0; mt < 4; mt++) {
            int r0 = m0 + wm * 64 + mt * 16 + g;
            #pragma unroll
            for (int nt = 0; nt < 8; nt++) {
                int ch = n0 + wn * 64 + nt * 8 + kin * 2;
                float v0 = acc[mt][nt][0] * alpha, v1 = acc[mt][nt][1] * alpha;
                float v2 = acc[mt][nt][2] * alpha, v3 = acc[mt][nt][3] * alpha;
                *(bf162*)(Cout + (size_t)r0 * ldc + ch) = __floats2bfloat162_rn(v0, v1);
                *(bf162*)(Cout + (size_t)(r0 + 8) * ldc + ch) = __floats2bfloat162_rn(v2, v3);
            }
        }
    } else if (EPI == 4) {
        // fused QKV epilogue
        const int which = n0 >> 9;            // 0=q, 1=k, 2=v
        if (which < 2) {
            bf16* Cout = g_qkv + (size_t)which * REG_SZ;
            const int nsub0 = n0 & 511;
            #pragma unroll
            for (int mt = 0; mt < 4; mt++) {
                int r0 = m0 + wm * 64 + mt * 16 + g;
                #pragma unroll
                for (int nt = 0; nt < 8; nt++) {
                    int cl = wn * 64 + nt * 8 + kin * 2;
                    float b0 = g_bqkv[n0 + cl], b1 = g_bqkv[n0 + cl + 1];
                    int ch = nsub0 + cl;
                    *(bf162*)(Cout + (size_t)r0 * CC + ch) =
                        __floats2bfloat162_rn(acc[mt][nt][0] + b0, acc[mt][nt][1] + b1);
                    *(bf162*)(Cout + (size_t)(r0 + 8) * CC + ch) =
                        __floats2bfloat162_rn(acc[mt][nt][2] + b0, acc[mt][nt][3] + b1);
                }
            }
        } else {
            // v: transposed bf16 store via smem, out layout [b][c][n]
            bf16* Cout = g_qkv + 2 * (size_t)REG_SZ;
            __syncthreads();
            bf16* tr = (bf16*)smem;
            #pragma unroll
            for (int mt = 0; mt < 4; mt++) {
                int tok = wm * 64 + mt * 16 + g;
                #pragma unroll
                for (int nt = 0; nt < 8; nt++) {
                    int cl = wn * 64 + nt * 8 + kin * 2;
                    float b0 = g_bqkv[n0 + cl], b1 = g_bqkv[n0 + cl + 1];
                    tr[(cl    ) * TRB_PITCH + tok    ] = __float2bfloat16_rn(acc[mt][nt][0] + b0);
                    tr[(cl + 1) * TRB_PITCH + tok    ] = __float2bfloat16_rn(acc[mt][nt][1] + b1);
                    tr[(cl    ) * TRB_PITCH + tok + 8] = __float2bfloat16_rn(acc[mt][nt][2] + b0);
                    tr[(cl + 1) * TRB_PITCH + tok + 8] = __float2bfloat16_rn(acc[mt][nt][3] + b1);
                }
            }
            __syncthreads();
            const int bidx = m0 >> 12;
            const int tok0 = m0 & 4095;
            const int vch0 = n0 - 1024;       // 0 or 256
            #pragma unroll 4
            for (int i = 0; i < 16; i++) {
                int idx = i * 256 + tid;
                int cl = idx >> 4, t8 = (idx & 15) * 8;
                uint4 v = *(uint4*)&tr[cl * TRB_PITCH + t8];
                *(uint4*)(Cout + ((size_t)bidx * CC + vch0 + cl) * HWN + tok0 + t8) = v;
            }
        }
    } else {
        // EPI 3: f32 transposed store + bias + residual
        float* Cout = (float*)Cout_ + (size_t)blockIdx.z * sC;
        __syncthreads();
        float* tr = (float*)smem;
        #pragma unroll
        for (int mt = 0; mt < 4; mt++) {
            int tok = wm * 64 + mt * 16 + g;
            #pragma unroll
            for (int nt = 0; nt < 8; nt++) {
                int ch = wn * 64 + nt * 8 + kin * 2;
                tr[(ch    ) * TRF_PITCH + tok    ] = acc[mt][nt][0];
                tr[(ch + 1) * TRF_PITCH + tok    ] = acc[mt][nt][1];
                tr[(ch    ) * TRF_PITCH + tok + 8] = acc[mt][nt][2];
                tr[(ch + 1) * TRF_PITCH + tok + 8] = acc[mt][nt][3];
            }
        }
        __syncthreads();
        const int bidx = m0 >> 12;
        const int tok0 = m0 & 4095;
        #pragma unroll 4
        for (int i = 0; i < 32; i++) {
            int idx = i * 256 + tid;
            int ch = idx >> 5, t4 = (idx & 31) * 4;
            float4 v = *(float4*)&tr[ch * TRF_PITCH + t4];
            float bv = bias[n0 + ch];
            v.x += bv; v.y += bv; v.z += bv; v.w += bv;
            size_t oidx = ((size_t)bidx * CC + n0 + ch) * HWN + tok0 + t4;
            float4 rr = *(const float4*)(resid + oidx);
            v.x += rr.x; v.y += rr.y; v.z += rr.z; v.w += rr.w;
            *(float4*)(Cout + oidx) = v;
        }
    }
}

// ---------------------------------------------------------------------------
// Round weights to bf16 (into packed g_w region)
// ---------------------------------------------------------------------------
__global__ void round_w_kernel(const float* __restrict__ src, bf16* __restrict__ dst) {
    int i = (blockIdx.x * 256 + threadIdx.x) * 4;
    float4 v = *(const float4*)(src + i);
    uint2 o;
    o.x = pack2(v.x, v.y);
    o.y = pack2(v.z, v.w);
    *(uint2*)(dst + i) = o;
}

// Pack q/k/v biases into g_bqkv
__global__ void bias_pack_kernel(const float* __restrict__ bq,
                                 const float* __restrict__ bk,
                                 const float* __restrict__ bv) {
    int i = blockIdx.x * 256 + threadIdx.x;   // 0..1535
    const float* src = (i < CC) ? bq : (i < 2 * CC) ? bk : bv;
    g_bqkv[i] = src[i & (CC - 1)];
}

// ---------------------------------------------------------------------------
// GroupNorm stats
// ---------------------------------------------------------------------------
__global__ void gn_stats_kernel(const float* __restrict__ x) {
    const int bg = blockIdx.x;
    const int b = bg / GG, g = bg % GG;
    const float* xp = x + ((size_t)b * CC + (size_t)g * CPG) * HWN;
    float s = 0.f, ss = 0.f;
    for (int i = threadIdx.x; i < CPG * HWN; i += 256) {
        float v = xp[i];
        s += v; ss += v * v;
    }
    __shared__ float sh1[256], sh2[256];
    sh1[threadIdx.x] = s; sh2[threadIdx.x] = ss;
    __syncthreads();
    for (int o = 128; o > 0; o >>= 1) {
        if (threadIdx.x < o) {
            sh1[threadIdx.x] += sh1[threadIdx.x + o];
            sh2[threadIdx.x] += sh2[threadIdx.x + o];
        }
        __syncthreads();
    }
    if (threadIdx.x == 0) {
        const float inv_n = 1.f / (CPG * HWN);
        float mu = sh1[0] * inv_n;
        float var = sh2[0] * inv_n - mu * mu;
        g_mu[bg] = mu;
        g_rstd[bg] = rsqrtf(var + EPSF);
    }
}

// ---------------------------------------------------------------------------
// Normalize + transpose -> h[b][n][c] bf16
// ---------------------------------------------------------------------------
__global__ void gn_norm_t_kernel(const float* __restrict__ x,
                                 const float* __restrict__ gamma,
                                 const float* __restrict__ beta) {
    __shared__ float tile[32][33];
    const int b = blockIdx.z;
    const int n0 = blockIdx.x * 32;
    const int c0 = blockIdx.y * 32;
    #pragma unroll
    for (int i = 0; i < 4; i++) {
        int c = c0 + threadIdx.y + i * 8;
        int n = n0 + threadIdx.x;
        float v = x[((size_t)b * CC + c) * HWN + n];
        int gidx = b * GG + (c / CPG);
        v = (v - g_mu[gidx]) * g_rstd[gidx] * gamma[c] + beta[c];
        tile[threadIdx.y + i * 8][threadIdx.x] = v;
    }
    __syncthreads();
    #pragma unroll
    for (int i = 0; i < 4; i++) {
        int n = n0 + threadIdx.y + i * 8;
        int c = c0 + threadIdx.x;
        g_h[((size_t)b * HWN + n) * CC + c] =
            __float2bfloat16_rn(tile[threadIdx.x][threadIdx.y + i * 8]);
    }
}

// ---------------------------------------------------------------------------
// Row softmax over 4096-wide bf16 rows (f32 internal)
// ---------------------------------------------------------------------------
__global__ void softmax_rows_kernel(bf16* __restrict__ S) {
    const size_t row = blockIdx.x;
    bf16* p = S + row * HWN;
    const int tid = threadIdx.x;

    uint4 u0 = ((const uint4*)p)[tid];
    uint4 u1 = ((const uint4*)p)[tid + 256];
    float vals[16];
    unpack2(u0.x, vals[0], vals[1]);  unpack2(u0.y, vals[2], vals[3]);
    unpack2(u0.z, vals[4], vals[5]);  unpack2(u0.w, vals[6], vals[7]);
    unpack2(u1.x, vals[8], vals[9]);  unpack2(u1.y, vals[10], vals[11]);
    unpack2(u1.z, vals[12], vals[13]); unpack2(u1.w, vals[14], vals[15]);

    float mx = -1e30f;
    #pragma unroll
    for (int i = 0; i < 16; i++) mx = fmaxf(mx, vals[i]);
    __shared__ float sh[256];
    sh[tid] = mx;
    __syncthreads();
    for (int o = 128; o > 0; o >>= 1) {
        if (tid < o) sh[tid] = fmaxf(sh[tid], sh[tid + o]);
        __syncthreads();
    }
    const float rmax = sh[0];
    __syncthreads();
    float sum = 0.f;
    #pragma unroll
    for (int i = 0; i < 16; i++) {
        vals[i] = __expf(vals[i] - rmax);
        sum += vals[i];
    }
    sh[tid] = sum;
    __syncthreads();
    for (int o = 128; o > 0; o >>= 1) {
        if (tid < o) sh[tid] += sh[tid + o];
        __syncthreads();
    }
    const float inv = 1.f / sh[0];
    #pragma unroll
    for (int i = 0; i < 16; i++) vals[i] *= inv;

    u0.x = pack2(vals[0], vals[1]);   u0.y = pack2(vals[2], vals[3]);
    u0.z = pack2(vals[4], vals[5]);   u0.w = pack2(vals[6], vals[7]);
    u1.x = pack2(vals[8], vals[9]);   u1.y = pack2(vals[10], vals[11]);
    u1.z = pack2(vals[12], vals[13]); u1.w = pack2(vals[14], vals[15]);
    ((uint4*)p)[tid] = u0;
    ((uint4*)p)[tid + 256] = u1;
}

// ---------------------------------------------------------------------------
// Launch
// ---------------------------------------------------------------------------
extern "C" void kernel_launch(void* const* d_in, const int* in_sizes, int n_in,
                              void* d_out, int out_size) {
    const float* x     = (const float*)d_in[0];
    const float* gamma = (const float*)d_in[1];
    const float* beta  = (const float*)d_in[2];
    const float* wq    = (const float*)d_in[3];
    const float* bq    = (const float*)d_in[4];
    const float* wk    = (const float*)d_in[5];
    const float* bk    = (const float*)d_in[6];
    const float* wv    = (const float*)d_in[7];
    const float* bv    = (const float*)d_in[8];
    const float* wo    = (const float*)d_in[9];
    const float* bo    = (const float*)d_in[10];
    float* out = (float*)d_out;

    bf16 *ph, *pqkv, *po, *ps, *pw;
    cudaGetSymbolAddress((void**)&ph, g_h);
    cudaGetSymbolAddress((void**)&pqkv, g_qkv);
    cudaGetSymbolAddress((void**)&po, g_o);
    cudaGetSymbolAddress((void**)&ps, g_s);
    cudaGetSymbolAddress((void**)&pw, g_w);

    cudaFuncSetAttribute(tgemm_kernel<1>, cudaFuncAttributeMaxDynamicSharedMemorySize, SMEM_BYTES);
    cudaFuncSetAttribute(tgemm_kernel<3>, cudaFuncAttributeMaxDynamicSharedMemorySize, SMEM_BYTES);
    cudaFuncSetAttribute(tgemm_kernel<4>, cudaFuncAttributeMaxDynamicSharedMemorySize, SMEM_BYTES);

    // 0) weights -> bf16 packed [wq|wk|wv|wo], biases packed
    const int wblk = CC * CC / (256 * 4);  // 256
    round_w_kernel<<<wblk, 256>>>(wq, pw + 0 * CC * CC);
    round_w_kernel<<<wblk, 256>>>(wk, pw + 1 * CC * CC);
    round_w_kernel<<<wblk, 256>>>(wv, pw + 2 * CC * CC);
    round_w_kernel<<<wblk, 256>>>(wo, pw + 3 * CC * CC);
    bias_pack_kernel<<<6, 256>>>(bq, bk, bv);

    // 1) GroupNorm
    gn_stats_kernel<<<BB * GG, 256>>>(x);
    gn_norm_t_kernel<<<dim3(HWN / 32, CC / 32, BB), dim3(32, 8)>>>(x, gamma, beta);

    const int Mflat = BB * HWN;

    // 2) fused QKV projection: [32768, 1536] = h @ [wq|wk|wv]^T
    dim3 gqkv(3 * CC / BN, Mflat / BM, 1);  // (6, 256)
    tgemm_kernel<4><<<gqkv, 256, SMEM_BYTES>>>(ph, pw, nullptr, nullptr, nullptr,
        CC, CC, 0, 0, 0, 0, CC / KC, 1.f);

    // 3) scores: S[b] = alpha * Q[b] K[b]^T  (bf16 out)
    dim3 gscore(HWN / BN, HWN / BM, BB);    // (16, 32, 8)
    tgemm_kernel<1><<<gscore, 256, SMEM_BYTES>>>(
        pqkv, pqkv + REG_SZ, nullptr, nullptr, ps,
        CC, CC, HWN,
        (size_t)HWN * CC, (size_t)HWN * CC, (size_t)HWN * HWN,
        CC / KC, ALPHAF);

    // 4) softmax (bf16 in/out)
    softmax_rows_kernel<<<BB * HWN, 256>>>(ps);

    // 5) O[b] = P[b] @ V[b]  (B = vT, K-major), bf16 out
    dim3 gsv(CC / BN, HWN / BM, BB);        // (2, 32, 8)
    tgemm_kernel<1><<<gsv, 256, SMEM_BYTES>>>(
        ps, pqkv + 2 * (size_t)REG_SZ, nullptr, nullptr, po,
        HWN, HWN, CC,
        (size_t)HWN * HWN, (size_t)CC * HWN, (size_t)HWN * CC,
        HWN / KC, 1.f);

    // 6) final projection + bias + residual, transposed -> [b][c][hw] f32
    dim3 gout(CC / BN, Mflat / BM, 1);      // (2, 256)
    tgemm_kernel<3><<<gout, 256, SMEM_BYTES>>>(po, pw + 3 * CC * CC, bo, x, out,
        CC, CC, CC, 0, 0, 0, CC / KC, 1.f);
}

// round 6
// speedup vs baseline: 7.5482x; 1.1405x over previous
#include <cuda_runtime.h>
#include <cuda.h>
#include <cuda_bf16.h>
#include <math.h>
#include <stdint.h>

// Problem constants
#define CC   512
#define HWN  4096
#define BB   8
#define GG   32
#define CPG  16
#define EPSF 1e-6f
#define ALPHAF 0.044194173824159216f

// GEMM tiling (bf16): 128x128 tile, 2 CTAs/SM
#define BM 128
#define BN 128
#define KC 64                          // bf16 elements per K chunk
#define STAGES 3
#define PITCHB  144                    // bytes per smem row (128 data + 16 pad)
#define STG_BYTES ((BM + BN) * PITCHB) // 36864
#define SMEM_BYTES (STAGES * STG_BYTES)  // 110592
#define TRB_PITCH 136                  // bf16 transpose pitch (bf16 units)
#define TRF_PITCH 132                  // f32 transpose pitch (f32 units)

#define REG_SZ (BB * HWN * CC)         // 16M elements per q/k/v region

typedef __nv_bfloat16 bf16;
typedef __nv_bfloat162 bf162;

// ---------------------------------------------------------------------------
// Device-global scratch
// ---------------------------------------------------------------------------
__device__ bf16 g_h[BB * HWN * CC];            // normalized [b][n][c]
__device__ bf16 g_qkv[3 * REG_SZ];             // q rowmaj | k rowmaj | vT [b][c][n]
__device__ bf16 g_o[BB * HWN * CC];            // attn out [b][n][c]
__device__ bf16 g_s[(size_t)BB * HWN * HWN];   // scores / probs (256MB)
__device__ bf16 g_w[4 * CC * CC];              // packed weights: wq|wk|wv|wo rows
__device__ float g_bqkv[3 * CC];               // packed biases bq|bk|bv
__device__ float g_mu[BB * GG];
__device__ float g_rstd[BB * GG];

// ---------------------------------------------------------------------------
// Helpers
// ---------------------------------------------------------------------------
__device__ __forceinline__ uint32_t smem_u32(const void* p) {
    uint32_t a;
    asm("{ .reg .u64 t; cvta.to.shared.u64 t, %1; cvt.u32.u64 %0, t; }"
        : "=r"(a) : "l"(p));
    return a;
}
__device__ __forceinline__ void cp_async16(uint32_t dst, const void* src) {
    asm volatile("cp.async.cg.shared.global [%0], [%1], 16;" :: "r"(dst), "l"(src));
}
__device__ __forceinline__ void cp_commit() {
    asm volatile("cp.async.commit_group;");
}
__device__ __forceinline__ void mma_bf16(float* d, const uint32_t* a, const uint32_t* b) {
    asm volatile(
        "mma.sync.aligned.m16n8k16.row.col.f32.bf16.bf16.f32 "
        "{%0,%1,%2,%3},{%4,%5,%6,%7},{%8,%9},{%0,%1,%2,%3};"
        : "+f"(d[0]), "+f"(d[1]), "+f"(d[2]), "+f"(d[3])
        : "r"(a[0]), "r"(a[1]), "r"(a[2]), "r"(a[3]), "r"(b[0]), "r"(b[1]));
}
#define LDSM4(r0, r1, r2, r3, addr) \
    asm volatile("ldmatrix.sync.aligned.m8n8.x4.shared.b16 {%0,%1,%2,%3}, [%4];" \
        : "=r"(r0), "=r"(r1), "=r"(r2), "=r"(r3) : "r"(addr))

__device__ __forceinline__ void unpack2(uint32_t w, float& x, float& y) {
    bf162 h = *reinterpret_cast<bf162*>(&w);
    float2 f = __bfloat1622float2(h);
    x = f.x; y = f.y;
}
__device__ __forceinline__ uint32_t pack2(float x, float y) {
    bf162 h = __floats2bfloat162_rn(x, y);
    return *reinterpret_cast<uint32_t*>(&h);
}

// ---------------------------------------------------------------------------
// bf16 tensor-core GEMM (128x128 tile, 2 CTAs/SM):
//   C[M,N] = A[M,K] * B[N,K]^T  (both K-major bf16)
//  EPI 1: * alpha, bf16 row-major store (scores, SV)
//  EPI 3: transposed f32 store out[b][ch][tok] = acc + bias + resid (final)
//  EPI 4: fused QKV epilogue (q/k row-major, v transposed; device symbols)
// ---------------------------------------------------------------------------
template <int EPI>
__global__ void __launch_bounds__(256, 2)
tgemm_kernel(const bf16* __restrict__ A, const bf16* __restrict__ Bm,
             const float* __restrict__ bias, const float* __restrict__ resid,
             void* __restrict__ Cout_,
             int lda, int ldb, int ldc,
             size_t sA, size_t sB, size_t sC,
             int NC, float alpha)
{
    extern __shared__ char smem[];
    const uint32_t smem_base = smem_u32(smem);
    const int tid = threadIdx.x;
    const int wid = tid >> 5;
    const int lane = tid & 31;
    const int g = lane >> 2;       // groupID 0..7
    const int kin = lane & 3;      // thread-in-group 0..3
    const int wm = wid & 1;        // warp m index (2) -> 64 rows
    const int wn = wid >> 1;       // warp n index (4) -> 32 cols

    const int m0 = blockIdx.y * BM;
    const int n0 = blockIdx.x * BN;
    A  += (size_t)blockIdx.z * sA;
    Bm += (size_t)blockIdx.z * sB;

    // ldmatrix per-thread byte offsets (within a stage)
    const int lq = lane >> 3;      // 0..3 quadrant selector
    const int lr = lane & 7;       // row within matrix
    uint32_t aoff[4], boff[2];
    #pragma unroll
    for (int mt = 0; mt < 4; mt++)
        aoff[mt] = (uint32_t)((wm * 64 + mt * 16 + (lq & 1) * 8 + lr) * PITCHB
                              + (lq >> 1) * 16);
    #pragma unroll
    for (int p = 0; p < 2; p++)
        boff[p] = (uint32_t)(BM * PITCHB
                             + (wn * 32 + (2 * p + (lq >> 1)) * 8 + lr) * PITCHB
                             + (lq & 1) * 16);

    float acc[4][4][4];
    #pragma unroll
    for (int mt = 0; mt < 4; mt++)
        #pragma unroll
        for (int nt = 0; nt < 4; nt++)
            #pragma unroll
            for (int c = 0; c < 4; c++) acc[mt][nt][c] = 0.f;

    // ---- prefetch first STAGES-1 chunks ----
    #pragma unroll
    for (int s = 0; s < STAGES - 1; s++) {
        const int k0 = s * KC;
        const uint32_t sb = smem_base + s * STG_BYTES;
        #pragma unroll
        for (int i = 0; i < 4; i++) {
            int idx = i * 256 + tid;
            int row = idx >> 3, kq = idx & 7;
            cp_async16(sb + row * PITCHB + kq * 16,
                       A + (size_t)(m0 + row) * lda + k0 + kq * 8);
        }
        #pragma unroll
        for (int i = 0; i < 4; i++) {
            int idx = i * 256 + tid;
            int row = idx >> 3, kq = idx & 7;
            cp_async16(sb + BM * PITCHB + row * PITCHB + kq * 16,
                       Bm + (size_t)(n0 + row) * ldb + k0 + kq * 8);
        }
        cp_commit();
    }

    // ---- main loop ----
    for (int c = 0; c < NC; c++) {
        asm volatile("cp.async.wait_group %0;" :: "n"(STAGES - 2));
        __syncthreads();

        const int pf = c + STAGES - 1;
        if (pf < NC) {
            const int k0 = pf * KC;
            const uint32_t sb = smem_base + (pf % STAGES) * STG_BYTES;
            #pragma unroll
            for (int i = 0; i < 4; i++) {
                int idx = i * 256 + tid;
                int row = idx >> 3, kq = idx & 7;
                cp_async16(sb + row * PITCHB + kq * 16,
                           A + (size_t)(m0 + row) * lda + k0 + kq * 8);
            }
            #pragma unroll
            for (int i = 0; i < 4; i++) {
                int idx = i * 256 + tid;
                int row = idx >> 3, kq = idx & 7;
                cp_async16(sb + BM * PITCHB + row * PITCHB + kq * 16,
                           Bm + (size_t)(n0 + row) * ldb + k0 + kq * 8);
            }
            cp_commit();
        }

        const uint32_t sb = smem_base + (c % STAGES) * STG_BYTES;
        #pragma unroll
        for (int ks = 0; ks < 4; ks++) {           // 4 x k16 per KC=64
            const uint32_t kb = sb + ks * 32;
            uint32_t af[4][4];
            #pragma unroll
            for (int mt = 0; mt < 4; mt++)
                LDSM4(af[mt][0], af[mt][1], af[mt][2], af[mt][3], kb + aoff[mt]);
            uint32_t bf[4][2];
            #pragma unroll
            for (int p = 0; p < 2; p++)
                LDSM4(bf[2 * p][0], bf[2 * p][1], bf[2 * p + 1][0], bf[2 * p + 1][1],
                      kb + boff[p]);
            #pragma unroll
            for (int mt = 0; mt < 4; mt++)
                #pragma unroll
                for (int nt = 0; nt < 4; nt++)
                    mma_bf16(acc[mt][nt], af[mt], bf[nt]);
        }
    }

    // ---- epilogue ----
    if (EPI == 1) {
        bf16* Cout = (bf16*)Cout_ + (size_t)blockIdx.z * sC;
        #pragma unroll
        for (int mt = 0; mt < 4; mt++) {
            int r0 = m0 + wm * 64 + mt * 16 + g;
            #pragma unroll
            for (int nt = 0; nt < 4; nt++) {
                int ch = n0 + wn * 32 + nt * 8 + kin * 2;
                float v0 = acc[mt][nt][0] * alpha, v1 = acc[mt][nt][1] * alpha;
                float v2 = acc[mt][nt][2] * alpha, v3 = acc[mt][nt][3] * alpha;
                *(bf162*)(Cout + (size_t)r0 * ldc + ch) = __floats2bfloat162_rn(v0, v1);
                *(bf162*)(Cout + (size_t)(r0 + 8) * ldc + ch) = __floats2bfloat162_rn(v2, v3);
            }
        }
    } else if (EPI == 4) {
        // fused QKV epilogue; n0 in [0, 1536), tiles of 128
        const int which = n0 >> 9;            // 0=q, 1=k, 2=v
        if (which < 2) {
            bf16* Cout = g_qkv + (size_t)which * REG_SZ;
            const int nsub0 = n0 & 511;
            #pragma unroll
            for (int mt = 0; mt < 4; mt++) {
                int r0 = m0 + wm * 64 + mt * 16 + g;
                #pragma unroll
                for (int nt = 0; nt < 4; nt++) {
                    int cl = wn * 32 + nt * 8 + kin * 2;
                    float b0 = g_bqkv[n0 + cl], b1 = g_bqkv[n0 + cl + 1];
                    int ch = nsub0 + cl;
                    *(bf162*)(Cout + (size_t)r0 * CC + ch) =
                        __floats2bfloat162_rn(acc[mt][nt][0] + b0, acc[mt][nt][1] + b1);
                    *(bf162*)(Cout + (size_t)(r0 + 8) * CC + ch) =
                        __floats2bfloat162_rn(acc[mt][nt][2] + b0, acc[mt][nt][3] + b1);
                }
            }
        } else {
            // v: transposed bf16 store via smem, out layout [b][c][n]
            bf16* Cout = g_qkv + 2 * (size_t)REG_SZ;
            __syncthreads();
            bf16* tr = (bf16*)smem;
            #pragma unroll
            for (int mt = 0; mt < 4; mt++) {
                int tok = wm * 64 + mt * 16 + g;
                #pragma unroll
                for (int nt = 0; nt < 4; nt++) {
                    int cl = wn * 32 + nt * 8 + kin * 2;
                    float b0 = g_bqkv[n0 + cl], b1 = g_bqkv[n0 + cl + 1];
                    tr[(cl    ) * TRB_PITCH + tok    ] = __float2bfloat16_rn(acc[mt][nt][0] + b0);
                    tr[(cl + 1) * TRB_PITCH + tok    ] = __float2bfloat16_rn(acc[mt][nt][1] + b1);
                    tr[(cl    ) * TRB_PITCH + tok + 8] = __float2bfloat16_rn(acc[mt][nt][2] + b0);
                    tr[(cl + 1) * TRB_PITCH + tok + 8] = __float2bfloat16_rn(acc[mt][nt][3] + b1);
                }
            }
            __syncthreads();
            const int bidx = m0 >> 12;
            const int tok0 = m0 & 4095;
            const int vch0 = n0 - 1024;       // 0,128,256,384
            #pragma unroll
            for (int i = 0; i < 8; i++) {
                int idx = i * 256 + tid;
                int cl = idx >> 4, t8 = (idx & 15) * 8;
                uint4 v = *(uint4*)&tr[cl * TRB_PITCH + t8];
                *(uint4*)(Cout + ((size_t)bidx * CC + vch0 + cl) * HWN + tok0 + t8) = v;
            }
        }
    } else {
        // EPI 3: f32 transposed store + bias + residual
        float* Cout = (float*)Cout_ + (size_t)blockIdx.z * sC;
        __syncthreads();
        float* tr = (float*)smem;
        #pragma unroll
        for (int mt = 0; mt < 4; mt++) {
            int tok = wm * 64 + mt * 16 + g;
            #pragma unroll
            for (int nt = 0; nt < 4; nt++) {
                int ch = wn * 32 + nt * 8 + kin * 2;
                tr[(ch    ) * TRF_PITCH + tok    ] = acc[mt][nt][0];
                tr[(ch + 1) * TRF_PITCH + tok    ] = acc[mt][nt][1];
                tr[(ch    ) * TRF_PITCH + tok + 8] = acc[mt][nt][2];
                tr[(ch + 1) * TRF_PITCH + tok + 8] = acc[mt][nt][3];
            }
        }
        __syncthreads();
        const int bidx = m0 >> 12;
        const int tok0 = m0 & 4095;
        #pragma unroll
        for (int i = 0; i < 16; i++) {
            int idx = i * 256 + tid;
            int ch = idx >> 5, t4 = (idx & 31) * 4;
            float4 v = *(float4*)&tr[ch * TRF_PITCH + t4];
            float bv = bias[n0 + ch];
            v.x += bv; v.y += bv; v.z += bv; v.w += bv;
            size_t oidx = ((size_t)bidx * CC + n0 + ch) * HWN + tok0 + t4;
            float4 rr = *(const float4*)(resid + oidx);
            v.x += rr.x; v.y += rr.y; v.z += rr.z; v.w += rr.w;
            *(float4*)(Cout + oidx) = v;
        }
    }
}

// ---------------------------------------------------------------------------
// Round weights to bf16 (into packed g_w region)
// ---------------------------------------------------------------------------
__global__ void round_w_kernel(const float* __restrict__ src, bf16* __restrict__ dst) {
    int i = (blockIdx.x * 256 + threadIdx.x) * 4;
    float4 v = *(const float4*)(src + i);
    uint2 o;
    o.x = pack2(v.x, v.y);
    o.y = pack2(v.z, v.w);
    *(uint2*)(dst + i) = o;
}

// Pack q/k/v biases into g_bqkv
__global__ void bias_pack_kernel(const float* __restrict__ bq,
                                 const float* __restrict__ bk,
                                 const float* __restrict__ bv) {
    int i = blockIdx.x * 256 + threadIdx.x;   // 0..1535
    const float* src = (i < CC) ? bq : (i < 2 * CC) ? bk : bv;
    g_bqkv[i] = src[i & (CC - 1)];
}

// ---------------------------------------------------------------------------
// GroupNorm stats
// ---------------------------------------------------------------------------
__global__ void gn_stats_kernel(const float* __restrict__ x) {
    const int bg = blockIdx.x;
    const int b = bg / GG, g = bg % GG;
    const float* xp = x + ((size_t)b * CC + (size_t)g * CPG) * HWN;
    float s = 0.f, ss = 0.f;
    for (int i = threadIdx.x; i < CPG * HWN; i += 256) {
        float v = xp[i];
        s += v; ss += v * v;
    }
    __shared__ float sh1[256], sh2[256];
    sh1[threadIdx.x] = s; sh2[threadIdx.x] = ss;
    __syncthreads();
    for (int o = 128; o > 0; o >>= 1) {
        if (threadIdx.x < o) {
            sh1[threadIdx.x] += sh1[threadIdx.x + o];
            sh2[threadIdx.x] += sh2[threadIdx.x + o];
        }
        __syncthreads();
    }
    if (threadIdx.x == 0) {
        const float inv_n = 1.f / (CPG * HWN);
        float mu = sh1[0] * inv_n;
        float var = sh2[0] * inv_n - mu * mu;
        g_mu[bg] = mu;
        g_rstd[bg] = rsqrtf(var + EPSF);
    }
}

// ---------------------------------------------------------------------------
// Normalize + transpose -> h[b][n][c] bf16
// ---------------------------------------------------------------------------
__global__ void gn_norm_t_kernel(const float* __restrict__ x,
                                 const float* __restrict__ gamma,
                                 const float* __restrict__ beta) {
    __shared__ float tile[32][33];
    const int b = blockIdx.z;
    const int n0 = blockIdx.x * 32;
    const int c0 = blockIdx.y * 32;
    #pragma unroll
    for (int i = 0; i < 4; i++) {
        int c = c0 + threadIdx.y + i * 8;
        int n = n0 + threadIdx.x;
        float v = x[((size_t)b * CC + c) * HWN + n];
        int gidx = b * GG + (c / CPG);
        v = (v - g_mu[gidx]) * g_rstd[gidx] * gamma[c] + beta[c];
        tile[threadIdx.y + i * 8][threadIdx.x] = v;
    }
    __syncthreads();
    #pragma unroll
    for (int i = 0; i < 4; i++) {
        int n = n0 + threadIdx.y + i * 8;
        int c = c0 + threadIdx.x;
        g_h[((size_t)b * HWN + n) * CC + c] =
            __float2bfloat16_rn(tile[threadIdx.x][threadIdx.y + i * 8]);
    }
}

// ---------------------------------------------------------------------------
// Row softmax over 4096-wide bf16 rows (f32 internal)
// ---------------------------------------------------------------------------
__global__ void softmax_rows_kernel(bf16* __restrict__ S) {
    const size_t row = blockIdx.x;
    bf16* p = S + row * HWN;
    const int tid = threadIdx.x;

    uint4 u0 = ((const uint4*)p)[tid];
    uint4 u1 = ((const uint4*)p)[tid + 256];
    float vals[16];
    unpack2(u0.x, vals[0], vals[1]);  unpack2(u0.y, vals[2], vals[3]);
    unpack2(u0.z, vals[4], vals[5]);  unpack2(u0.w, vals[6], vals[7]);
    unpack2(u1.x, vals[8], vals[9]);  unpack2(u1.y, vals[10], vals[11]);
    unpack2(u1.z, vals[12], vals[13]); unpack2(u1.w, vals[14], vals[15]);

    float mx = -1e30f;
    #pragma unroll
    for (int i = 0; i < 16; i++) mx = fmaxf(mx, vals[i]);
    __shared__ float sh[256];
    sh[tid] = mx;
    __syncthreads();
    for (int o = 128; o > 0; o >>= 1) {
        if (tid < o) sh[tid] = fmaxf(sh[tid], sh[tid + o]);
        __syncthreads();
    }
    const float rmax = sh[0];
    __syncthreads();
    float sum = 0.f;
    #pragma unroll
    for (int i = 0; i < 16; i++) {
        vals[i] = __expf(vals[i] - rmax);
        sum += vals[i];
    }
    sh[tid] = sum;
    __syncthreads();
    for (int o = 128; o > 0; o >>= 1) {
        if (tid < o) sh[tid] += sh[tid + o];
        __syncthreads();
    }
    const float inv = 1.f / sh[0];
    #pragma unroll
    for (int i = 0; i < 16; i++) vals[i] *= inv;

    u0.x = pack2(vals[0], vals[1]);   u0.y = pack2(vals[2], vals[3]);
    u0.z = pack2(vals[4], vals[5]);   u0.w = pack2(vals[6], vals[7]);
    u1.x = pack2(vals[8], vals[9]);   u1.y = pack2(vals[10], vals[11]);
    u1.z = pack2(vals[12], vals[13]); u1.w = pack2(vals[14], vals[15]);
    ((uint4*)p)[tid] = u0;
    ((uint4*)p)[tid + 256] = u1;
}

// ---------------------------------------------------------------------------
// Launch
// ---------------------------------------------------------------------------
extern "C" void kernel_launch(void* const* d_in, const int* in_sizes, int n_in,
                              void* d_out, int out_size) {
    const float* x     = (const float*)d_in[0];
    const float* gamma = (const float*)d_in[1];
    const float* beta  = (const float*)d_in[2];
    const float* wq    = (const float*)d_in[3];
    const float* bq    = (const float*)d_in[4];
    const float* wk    = (const float*)d_in[5];
    const float* bk    = (const float*)d_in[6];
    const float* wv    = (const float*)d_in[7];
    const float* bv    = (const float*)d_in[8];
    const float* wo    = (const float*)d_in[9];
    const float* bo    = (const float*)d_in[10];
    float* out = (float*)d_out;

    bf16 *ph, *pqkv, *po, *ps, *pw;
    cudaGetSymbolAddress((void**)&ph, g_h);
    cudaGetSymbolAddress((void**)&pqkv, g_qkv);
    cudaGetSymbolAddress((void**)&po, g_o);
    cudaGetSymbolAddress((void**)&ps, g_s);
    cudaGetSymbolAddress((void**)&pw, g_w);

    cudaFuncSetAttribute(tgemm_kernel<1>, cudaFuncAttributeMaxDynamicSharedMemorySize, SMEM_BYTES);
    cudaFuncSetAttribute(tgemm_kernel<3>, cudaFuncAttributeMaxDynamicSharedMemorySize, SMEM_BYTES);
    cudaFuncSetAttribute(tgemm_kernel<4>, cudaFuncAttributeMaxDynamicSharedMemorySize, SMEM_BYTES);

    // 0) weights -> bf16 packed [wq|wk|wv|wo], biases packed
    const int wblk = CC * CC / (256 * 4);  // 256
    round_w_kernel<<<wblk, 256>>>(wq, pw + 0 * CC * CC);
    round_w_kernel<<<wblk, 256>>>(wk, pw + 1 * CC * CC);
    round_w_kernel<<<wblk, 256>>>(wv, pw + 2 * CC * CC);
    round_w_kernel<<<wblk, 256>>>(wo, pw + 3 * CC * CC);
    bias_pack_kernel<<<6, 256>>>(bq, bk, bv);

    // 1) GroupNorm
    gn_stats_kernel<<<BB * GG, 256>>>(x);
    gn_norm_t_kernel<<<dim3(HWN / 32, CC / 32, BB), dim3(32, 8)>>>(x, gamma, beta);

    const int Mflat = BB * HWN;

    // 2) fused QKV projection: [32768, 1536] = h @ [wq|wk|wv]^T
    dim3 gqkv(3 * CC / BN, Mflat / BM, 1);  // (12, 256)
    tgemm_kernel<4><<<gqkv, 256, SMEM_BYTES>>>(ph, pw, nullptr, nullptr, nullptr,
        CC, CC, 0, 0, 0, 0, CC / KC, 1.f);

    // 3) scores: S[b] = alpha * Q[b] K[b]^T  (bf16 out)
    dim3 gscore(HWN / BN, HWN / BM, BB);    // (32, 32, 8)
    tgemm_kernel<1><<<gscore, 256, SMEM_BYTES>>>(
        pqkv, pqkv + REG_SZ, nullptr, nullptr, ps,
        CC, CC, HWN,
        (size_t)HWN * CC, (size_t)HWN * CC, (size_t)HWN * HWN,
        CC / KC, ALPHAF);

    // 4) softmax (bf16 in/out)
    softmax_rows_kernel<<<BB * HWN, 256>>>(ps);

    // 5) O[b] = P[b] @ V[b]  (B = vT, K-major), bf16 out
    dim3 gsv(CC / BN, HWN / BM, BB);        // (4, 32, 8)
    tgemm_kernel<1><<<gsv, 256, SMEM_BYTES>>>(
        ps, pqkv + 2 * (size_t)REG_SZ, nullptr, nullptr, po,
        HWN, HWN, CC,
        (size_t)HWN * HWN, (size_t)CC * HWN, (size_t)HWN * CC,
        HWN / KC, 1.f);

    // 6) final projection + bias + residual, transposed -> [b][c][hw] f32
    dim3 gout(CC / BN, Mflat / BM, 1);      // (4, 256)
    tgemm_kernel<3><<<gout, 256, SMEM_BYTES>>>(po, pw + 3 * CC * CC, bo, x, out,
        CC, CC, CC, 0, 0, 0, CC / KC, 1.f);
}

// round 7
// speedup vs baseline: 7.6867x; 1.0183x over previous
#include <cuda_runtime.h>
#include <cuda.h>
#include <cuda_bf16.h>
#include <math.h>
#include <stdint.h>

// Problem constants
#define CC   512
#define HWN  4096
#define BB   8
#define GG   32
#define CPG  16
#define EPSF 1e-6f
#define ALPHAF 0.044194173824159216f

// GEMM tiling (bf16): 128x128 tile, 2 CTAs/SM
#define BM 128
#define BN 128
#define KC 64                          // bf16 elements per K chunk
#define STAGES 3
#define PITCHB  144                    // bytes per smem row (128 data + 16 pad)
#define STG_BYTES ((BM + BN) * PITCHB) // 36864
#define SMEM_BYTES (STAGES * STG_BYTES)  // 110592
#define TRB_PITCH 136                  // bf16 transpose pitch (bf16 units)
#define TRF_PITCH 132                  // f32 transpose pitch (f32 units)

#define REG_SZ (BB * HWN * CC)         // 16M elements per q/k/v region
#define NTILES (HWN / BN)              // 32 n-tiles in scores GEMM

typedef __nv_bfloat16 bf16;
typedef __nv_bfloat162 bf162;

// ---------------------------------------------------------------------------
// Device-global scratch
// ---------------------------------------------------------------------------
__device__ bf16 g_h[BB * HWN * CC];            // normalized [b][n][c]
__device__ bf16 g_qkv[3 * REG_SZ];             // q rowmaj | k rowmaj | vT [b][c][n]
__device__ bf16 g_o[BB * HWN * CC];            // attn out [b][n][c]
__device__ bf16 g_s[(size_t)BB * HWN * HWN];   // unnorm probs exp(s) (256MB)
__device__ bf16 g_w[4 * CC * CC];              // packed weights: wq|wk|wv|wo rows
__device__ float g_bqkv[3 * CC];               // packed biases bq|bk|bv
__device__ float g_psum[(size_t)BB * NTILES * HWN];  // per-tile row sums (4MB)
__device__ float g_rinv[BB * HWN];             // reciprocal row sums
__device__ float g_mu[BB * GG];
__device__ float g_rstd[BB * GG];

// ---------------------------------------------------------------------------
// Helpers
// ---------------------------------------------------------------------------
__device__ __forceinline__ uint32_t smem_u32(const void* p) {
    uint32_t a;
    asm("{ .reg .u64 t; cvta.to.shared.u64 t, %1; cvt.u32.u64 %0, t; }"
        : "=r"(a) : "l"(p));
    return a;
}
__device__ __forceinline__ void cp_async16(uint32_t dst, const void* src) {
    asm volatile("cp.async.cg.shared.global [%0], [%1], 16;" :: "r"(dst), "l"(src));
}
__device__ __forceinline__ void cp_commit() {
    asm volatile("cp.async.commit_group;");
}
__device__ __forceinline__ void mma_bf16(float* d, const uint32_t* a, const uint32_t* b) {
    asm volatile(
        "mma.sync.aligned.m16n8k16.row.col.f32.bf16.bf16.f32 "
        "{%0,%1,%2,%3},{%4,%5,%6,%7},{%8,%9},{%0,%1,%2,%3};"
        : "+f"(d[0]), "+f"(d[1]), "+f"(d[2]), "+f"(d[3])
        : "r"(a[0]), "r"(a[1]), "r"(a[2]), "r"(a[3]), "r"(b[0]), "r"(b[1]));
}
#define LDSM4(r0, r1, r2, r3, addr) \
    asm volatile("ldmatrix.sync.aligned.m8n8.x4.shared.b16 {%0,%1,%2,%3}, [%4];" \
        : "=r"(r0), "=r"(r1), "=r"(r2), "=r"(r3) : "r"(addr))

__device__ __forceinline__ void unpack2(uint32_t w, float& x, float& y) {
    bf162 h = *reinterpret_cast<bf162*>(&w);
    float2 f = __bfloat1622float2(h);
    x = f.x; y = f.y;
}
__device__ __forceinline__ uint32_t pack2(float x, float y) {
    bf162 h = __floats2bfloat162_rn(x, y);
    return *reinterpret_cast<uint32_t*>(&h);
}

// ---------------------------------------------------------------------------
// bf16 tensor-core GEMM (128x128 tile, 2 CTAs/SM):
//   C[M,N] = A[M,K] * B[N,K]^T  (both K-major bf16)
//  EPI 3: transposed f32 store out[b][ch][tok] = acc + bias + resid (final)
//  EPI 4: fused QKV epilogue (q/k row-major, v transposed; device symbols)
//  EPI 5: scores: store exp(alpha*acc) bf16 + deterministic per-tile row sums
//  EPI 6: SV: store acc * rinv[row] (softmax normalization folded in)
// ---------------------------------------------------------------------------
template <int EPI>
__global__ void __launch_bounds__(256, 2)
tgemm_kernel(const bf16* __restrict__ A, const bf16* __restrict__ Bm,
             const float* __restrict__ bias, const float* __restrict__ resid,
             void* __restrict__ Cout_,
             int lda, int ldb, int ldc,
             size_t sA, size_t sB, size_t sC,
             int NC, float alpha)
{
    extern __shared__ char smem[];
    const uint32_t smem_base = smem_u32(smem);
    const int tid = threadIdx.x;
    const int wid = tid >> 5;
    const int lane = tid & 31;
    const int g = lane >> 2;       // groupID 0..7
    const int kin = lane & 3;      // thread-in-group 0..3
    const int wm = wid & 1;        // warp m index (2) -> 64 rows
    const int wn = wid >> 1;       // warp n index (4) -> 32 cols

    const int m0 = blockIdx.y * BM;
    const int n0 = blockIdx.x * BN;
    A  += (size_t)blockIdx.z * sA;
    Bm += (size_t)blockIdx.z * sB;

    // ldmatrix per-thread byte offsets (within a stage)
    const int lq = lane >> 3;      // 0..3 quadrant selector
    const int lr = lane & 7;       // row within matrix
    uint32_t aoff[4], boff[2];
    #pragma unroll
    for (int mt = 0; mt < 4; mt++)
        aoff[mt] = (uint32_t)((wm * 64 + mt * 16 + (lq & 1) * 8 + lr) * PITCHB
                              + (lq >> 1) * 16);
    #pragma unroll
    for (int p = 0; p < 2; p++)
        boff[p] = (uint32_t)(BM * PITCHB
                             + (wn * 32 + (2 * p + (lq >> 1)) * 8 + lr) * PITCHB
                             + (lq & 1) * 16);

    float acc[4][4][4];
    #pragma unroll
    for (int mt = 0; mt < 4; mt++)
        #pragma unroll
        for (int nt = 0; nt < 4; nt++)
            #pragma unroll
            for (int c = 0; c < 4; c++) acc[mt][nt][c] = 0.f;

    // ---- prefetch first STAGES-1 chunks ----
    #pragma unroll
    for (int s = 0; s < STAGES - 1; s++) {
        const int k0 = s * KC;
        const uint32_t sb = smem_base + s * STG_BYTES;
        #pragma unroll
        for (int i = 0; i < 4; i++) {
            int idx = i * 256 + tid;
            int row = idx >> 3, kq = idx & 7;
            cp_async16(sb + row * PITCHB + kq * 16,
                       A + (size_t)(m0 + row) * lda + k0 + kq * 8);
        }
        #pragma unroll
        for (int i = 0; i < 4; i++) {
            int idx = i * 256 + tid;
            int row = idx >> 3, kq = idx & 7;
            cp_async16(sb + BM * PITCHB + row * PITCHB + kq * 16,
                       Bm + (size_t)(n0 + row) * ldb + k0 + kq * 8);
        }
        cp_commit();
    }

    // ---- main loop ----
    for (int c = 0; c < NC; c++) {
        asm volatile("cp.async.wait_group %0;" :: "n"(STAGES - 2));
        __syncthreads();

        const int pf = c + STAGES - 1;
        if (pf < NC) {
            const int k0 = pf * KC;
            const uint32_t sb = smem_base + (pf % STAGES) * STG_BYTES;
            #pragma unroll
            for (int i = 0; i < 4; i++) {
                int idx = i * 256 + tid;
                int row = idx >> 3, kq = idx & 7;
                cp_async16(sb + row * PITCHB + kq * 16,
                           A + (size_t)(m0 + row) * lda + k0 + kq * 8);
            }
            #pragma unroll
            for (int i = 0; i < 4; i++) {
                int idx = i * 256 + tid;
                int row = idx >> 3, kq = idx & 7;
                cp_async16(sb + BM * PITCHB + row * PITCHB + kq * 16,
                           Bm + (size_t)(n0 + row) * ldb + k0 + kq * 8);
            }
            cp_commit();
        }

        const uint32_t sb = smem_base + (c % STAGES) * STG_BYTES;
        #pragma unroll
        for (int ks = 0; ks < 4; ks++) {           // 4 x k16 per KC=64
            const uint32_t kb = sb + ks * 32;
            uint32_t af[4][4];
            #pragma unroll
            for (int mt = 0; mt < 4; mt++)
                LDSM4(af[mt][0], af[mt][1], af[mt][2], af[mt][3], kb + aoff[mt]);
            uint32_t bf[4][2];
            #pragma unroll
            for (int p = 0; p < 2; p++)
                LDSM4(bf[2 * p][0], bf[2 * p][1], bf[2 * p + 1][0], bf[2 * p + 1][1],
                      kb + boff[p]);
            #pragma unroll
            for (int mt = 0; mt < 4; mt++)
                #pragma unroll
                for (int nt = 0; nt < 4; nt++)
                    mma_bf16(acc[mt][nt], af[mt], bf[nt]);
        }
    }

    // ---- epilogue ----
    if (EPI == 5) {
        // scores: P = exp(alpha*acc) bf16 + per-tile row sums (deterministic)
        bf16* Cout = (bf16*)Cout_ + (size_t)blockIdx.z * sC;
        __syncthreads();
        float (*sm)[5] = (float(*)[5])smem;   // [128][5] pad -> conflict-free
        #pragma unroll
        for (int mt = 0; mt < 4; mt++) {
            int rl = wm * 64 + mt * 16 + g;
            int r0 = m0 + rl;
            float s0 = 0.f, s1 = 0.f;
            #pragma unroll
            for (int nt = 0; nt < 4; nt++) {
                int ch = n0 + wn * 32 + nt * 8 + kin * 2;
                float e0 = __expf(alpha * acc[mt][nt][0]);
                float e1 = __expf(alpha * acc[mt][nt][1]);
                float e2 = __expf(alpha * acc[mt][nt][2]);
                float e3 = __expf(alpha * acc[mt][nt][3]);
                bf162 h01 = __floats2bfloat162_rn(e0, e1);
                bf162 h23 = __floats2bfloat162_rn(e2, e3);
                *(bf162*)(Cout + (size_t)r0 * ldc + ch) = h01;
                *(bf162*)(Cout + (size_t)(r0 + 8) * ldc + ch) = h23;
                float2 f01 = __bfloat1622float2(h01);   // sum the ROUNDED values
                float2 f23 = __bfloat1622float2(h23);
                s0 += f01.x + f01.y;
                s1 += f23.x + f23.y;
            }
            s0 += __shfl_xor_sync(0xffffffffu, s0, 1);
            s0 += __shfl_xor_sync(0xffffffffu, s0, 2);
            s1 += __shfl_xor_sync(0xffffffffu, s1, 1);
            s1 += __shfl_xor_sync(0xffffffffu, s1, 2);
            if (kin == 0) {
                sm[rl][wn] = s0;
                sm[rl + 8][wn] = s1;
            }
        }
        __syncthreads();
        if (tid < 128) {
            float t = sm[tid][0] + sm[tid][1] + sm[tid][2] + sm[tid][3];
            g_psum[((size_t)blockIdx.z * NTILES + blockIdx.x) * HWN + m0 + tid] = t;
        }
    } else if (EPI == 6) {
        // SV: normalize by reciprocal row sum
        bf16* Cout = (bf16*)Cout_ + (size_t)blockIdx.z * sC;
        const float* rinv = g_rinv + (size_t)blockIdx.z * HWN;
        #pragma unroll
        for (int mt = 0; mt < 4; mt++) {
            int r0 = m0 + wm * 64 + mt * 16 + g;
            float i0 = rinv[r0], i1 = rinv[r0 + 8];
            #pragma unroll
            for (int nt = 0; nt < 4; nt++) {
                int ch = n0 + wn * 32 + nt * 8 + kin * 2;
                *(bf162*)(Cout + (size_t)r0 * ldc + ch) =
                    __floats2bfloat162_rn(acc[mt][nt][0] * i0, acc[mt][nt][1] * i0);
                *(bf162*)(Cout + (size_t)(r0 + 8) * ldc + ch) =
                    __floats2bfloat162_rn(acc[mt][nt][2] * i1, acc[mt][nt][3] * i1);
            }
        }
    } else if (EPI == 4) {
        // fused QKV epilogue; n0 in [0, 1536), tiles of 128
        const int which = n0 >> 9;            // 0=q, 1=k, 2=v
        if (which < 2) {
            bf16* Cout = g_qkv + (size_t)which * REG_SZ;
            const int nsub0 = n0 & 511;
            #pragma unroll
            for (int mt = 0; mt < 4; mt++) {
                int r0 = m0 + wm * 64 + mt * 16 + g;
                #pragma unroll
                for (int nt = 0; nt < 4; nt++) {
                    int cl = wn * 32 + nt * 8 + kin * 2;
                    float b0 = g_bqkv[n0 + cl], b1 = g_bqkv[n0 + cl + 1];
                    int ch = nsub0 + cl;
                    *(bf162*)(Cout + (size_t)r0 * CC + ch) =
                        __floats2bfloat162_rn(acc[mt][nt][0] + b0, acc[mt][nt][1] + b1);
                    *(bf162*)(Cout + (size_t)(r0 + 8) * CC + ch) =
                        __floats2bfloat162_rn(acc[mt][nt][2] + b0, acc[mt][nt][3] + b1);
                }
            }
        } else {
            // v: transposed bf16 store via smem, out layout [b][c][n]
            bf16* Cout = g_qkv + 2 * (size_t)REG_SZ;
            __syncthreads();
            bf16* tr = (bf16*)smem;
            #pragma unroll
            for (int mt = 0; mt < 4; mt++) {
                int tok = wm * 64 + mt * 16 + g;
                #pragma unroll
                for (int nt = 0; nt < 4; nt++) {
                    int cl = wn * 32 + nt * 8 + kin * 2;
                    float b0 = g_bqkv[n0 + cl], b1 = g_bqkv[n0 + cl + 1];
                    tr[(cl    ) * TRB_PITCH + tok    ] = __float2bfloat16_rn(acc[mt][nt][0] + b0);
                    tr[(cl + 1) * TRB_PITCH + tok    ] = __float2bfloat16_rn(acc[mt][nt][1] + b1);
                    tr[(cl    ) * TRB_PITCH + tok + 8] = __float2bfloat16_rn(acc[mt][nt][2] + b0);
                    tr[(cl + 1) * TRB_PITCH + tok + 8] = __float2bfloat16_rn(acc[mt][nt][3] + b1);
                }
            }
            __syncthreads();
            const int bidx = m0 >> 12;
            const int tok0 = m0 & 4095;
            const int vch0 = n0 - 1024;       // 0,128,256,384
            #pragma unroll
            for (int i = 0; i < 8; i++) {
                int idx = i * 256 + tid;
                int cl = idx >> 4, t8 = (idx & 15) * 8;
                uint4 v = *(uint4*)&tr[cl * TRB_PITCH + t8];
                *(uint4*)(Cout + ((size_t)bidx * CC + vch0 + cl) * HWN + tok0 + t8) = v;
            }
        }
    } else {
        // EPI 3: f32 transposed store + bias + residual
        float* Cout = (float*)Cout_ + (size_t)blockIdx.z * sC;
        __syncthreads();
        float* tr = (float*)smem;
        #pragma unroll
        for (int mt = 0; mt < 4; mt++) {
            int tok = wm * 64 + mt * 16 + g;
            #pragma unroll
            for (int nt = 0; nt < 4; nt++) {
                int ch = wn * 32 + nt * 8 + kin * 2;
                tr[(ch    ) * TRF_PITCH + tok    ] = acc[mt][nt][0];
                tr[(ch + 1) * TRF_PITCH + tok    ] = acc[mt][nt][1];
                tr[(ch    ) * TRF_PITCH + tok + 8] = acc[mt][nt][2];
                tr[(ch + 1) * TRF_PITCH + tok + 8] = acc[mt][nt][3];
            }
        }
        __syncthreads();
        const int bidx = m0 >> 12;
        const int tok0 = m0 & 4095;
        #pragma unroll
        for (int i = 0; i < 16; i++) {
            int idx = i * 256 + tid;
            int ch = idx >> 5, t4 = (idx & 31) * 4;
            float4 v = *(float4*)&tr[ch * TRF_PITCH + t4];
            float bv = bias[n0 + ch];
            v.x += bv; v.y += bv; v.z += bv; v.w += bv;
            size_t oidx = ((size_t)bidx * CC + n0 + ch) * HWN + tok0 + t4;
            float4 rr = *(const float4*)(resid + oidx);
            v.x += rr.x; v.y += rr.y; v.z += rr.z; v.w += rr.w;
            *(float4*)(Cout + oidx) = v;
        }
    }
}

// ---------------------------------------------------------------------------
// Reciprocal row sums: g_rinv[b][row] = 1 / sum_t g_psum[b][t][row]
// ---------------------------------------------------------------------------
__global__ void rinv_kernel() {
    int idx = blockIdx.x * 256 + threadIdx.x;   // 0..BB*HWN-1
    int b = idx >> 12;
    int row = idx & (HWN - 1);
    const float* p = g_psum + (size_t)b * NTILES * HWN + row;
    float s = 0.f;
    #pragma unroll
    for (int t = 0; t < NTILES; t++) s += p[(size_t)t * HWN];
    g_rinv[idx] = 1.f / s;
}

// ---------------------------------------------------------------------------
// Round weights to bf16 (into packed g_w region)
// ---------------------------------------------------------------------------
__global__ void round_w_kernel(const float* __restrict__ src, bf16* __restrict__ dst) {
    int i = (blockIdx.x * 256 + threadIdx.x) * 4;
    float4 v = *(const float4*)(src + i);
    uint2 o;
    o.x = pack2(v.x, v.y);
    o.y = pack2(v.z, v.w);
    *(uint2*)(dst + i) = o;
}

// Pack q/k/v biases into g_bqkv
__global__ void bias_pack_kernel(const float* __restrict__ bq,
                                 const float* __restrict__ bk,
                                 const float* __restrict__ bv) {
    int i = blockIdx.x * 256 + threadIdx.x;   // 0..1535
    const float* src = (i < CC) ? bq : (i < 2 * CC) ? bk : bv;
    g_bqkv[i] = src[i & (CC - 1)];
}

// ---------------------------------------------------------------------------
// GroupNorm stats
// ---------------------------------------------------------------------------
__global__ void gn_stats_kernel(const float* __restrict__ x) {
    const int bg = blockIdx.x;
    const int b = bg / GG, g = bg % GG;
    const float* xp = x + ((size_t)b * CC + (size_t)g * CPG) * HWN;
    float s = 0.f, ss = 0.f;
    for (int i = threadIdx.x; i < CPG * HWN; i += 256) {
        float v = xp[i];
        s += v; ss += v * v;
    }
    __shared__ float sh1[256], sh2[256];
    sh1[threadIdx.x] = s; sh2[threadIdx.x] = ss;
    __syncthreads();
    for (int o = 128; o > 0; o >>= 1) {
        if (threadIdx.x < o) {
            sh1[threadIdx.x] += sh1[threadIdx.x + o];
            sh2[threadIdx.x] += sh2[threadIdx.x + o];
        }
        __syncthreads();
    }
    if (threadIdx.x == 0) {
        const float inv_n = 1.f / (CPG * HWN);
        float mu = sh1[0] * inv_n;
        float var = sh2[0] * inv_n - mu * mu;
        g_mu[bg] = mu;
        g_rstd[bg] = rsqrtf(var + EPSF);
    }
}

// ---------------------------------------------------------------------------
// Normalize + transpose -> h[b][n][c] bf16
// ---------------------------------------------------------------------------
__global__ void gn_norm_t_kernel(const float* __restrict__ x,
                                 const float* __restrict__ gamma,
                                 const float* __restrict__ beta) {
    __shared__ float tile[32][33];
    const int b = blockIdx.z;
    const int n0 = blockIdx.x * 32;
    const int c0 = blockIdx.y * 32;
    #pragma unroll
    for (int i = 0; i < 4; i++) {
        int c = c0 + threadIdx.y + i * 8;
        int n = n0 + threadIdx.x;
        float v = x[((size_t)b * CC + c) * HWN + n];
        int gidx = b * GG + (c / CPG);
        v = (v - g_mu[gidx]) * g_rstd[gidx] * gamma[c] + beta[c];
        tile[threadIdx.y + i * 8][threadIdx.x] = v;
    }
    __syncthreads();
    #pragma unroll
    for (int i = 0; i < 4; i++) {
        int n = n0 + threadIdx.y + i * 8;
        int c = c0 + threadIdx.x;
        g_h[((size_t)b * HWN + n) * CC + c] =
            __float2bfloat16_rn(tile[threadIdx.x][threadIdx.y + i * 8]);
    }
}

// ---------------------------------------------------------------------------
// Launch
// ---------------------------------------------------------------------------
extern "C" void kernel_launch(void* const* d_in, const int* in_sizes, int n_in,
                              void* d_out, int out_size) {
    const float* x     = (const float*)d_in[0];
    const float* gamma = (const float*)d_in[1];
    const float* beta  = (const float*)d_in[2];
    const float* wq    = (const float*)d_in[3];
    const float* bq    = (const float*)d_in[4];
    const float* wk    = (const float*)d_in[5];
    const float* bk    = (const float*)d_in[6];
    const float* wv    = (const float*)d_in[7];
    const float* bv    = (const float*)d_in[8];
    const float* wo    = (const float*)d_in[9];
    const float* bo    = (const float*)d_in[10];
    float* out = (float*)d_out;

    bf16 *ph, *pqkv, *po, *ps, *pw;
    cudaGetSymbolAddress((void**)&ph, g_h);
    cudaGetSymbolAddress((void**)&pqkv, g_qkv);
    cudaGetSymbolAddress((void**)&po, g_o);
    cudaGetSymbolAddress((void**)&ps, g_s);
    cudaGetSymbolAddress((void**)&pw, g_w);

    cudaFuncSetAttribute(tgemm_kernel<3>, cudaFuncAttributeMaxDynamicSharedMemorySize, SMEM_BYTES);
    cudaFuncSetAttribute(tgemm_kernel<4>, cudaFuncAttributeMaxDynamicSharedMemorySize, SMEM_BYTES);
    cudaFuncSetAttribute(tgemm_kernel<5>, cudaFuncAttributeMaxDynamicSharedMemorySize, SMEM_BYTES);
    cudaFuncSetAttribute(tgemm_kernel<6>, cudaFuncAttributeMaxDynamicSharedMemorySize, SMEM_BYTES);

    // 0) weights -> bf16 packed [wq|wk|wv|wo], biases packed
    const int wblk = CC * CC / (256 * 4);  // 256
    round_w_kernel<<<wblk, 256>>>(wq, pw + 0 * CC * CC);
    round_w_kernel<<<wblk, 256>>>(wk, pw + 1 * CC * CC);
    round_w_kernel<<<wblk, 256>>>(wv, pw + 2 * CC * CC);
    round_w_kernel<<<wblk, 256>>>(wo, pw + 3 * CC * CC);
    bias_pack_kernel<<<6, 256>>>(bq, bk, bv);

    // 1) GroupNorm
    gn_stats_kernel<<<BB * GG, 256>>>(x);
    gn_norm_t_kernel<<<dim3(HWN / 32, CC / 32, BB), dim3(32, 8)>>>(x, gamma, beta);

    const int Mflat = BB * HWN;

    // 2) fused QKV projection: [32768, 1536] = h @ [wq|wk|wv]^T
    dim3 gqkv(3 * CC / BN, Mflat / BM, 1);  // (12, 256)
    tgemm_kernel<4><<<gqkv, 256, SMEM_BYTES>>>(ph, pw, nullptr, nullptr, nullptr,
        CC, CC, 0, 0, 0, 0, CC / KC, 1.f);

    // 3) scores + exp + row-sum partials: P = exp(alpha * Q K^T)
    dim3 gscore(HWN / BN, HWN / BM, BB);    // (32, 32, 8)
    tgemm_kernel<5><<<gscore, 256, SMEM_BYTES>>>(
        pqkv, pqkv + REG_SZ, nullptr, nullptr, ps,
        CC, CC, HWN,
        (size_t)HWN * CC, (size_t)HWN * CC, (size_t)HWN * HWN,
        CC / KC, ALPHAF);

    // 4) reciprocal row sums (replaces softmax kernel)
    rinv_kernel<<<BB * HWN / 256, 256>>>();

    // 5) O[b] = (P[b] @ V[b]) * rinv  (B = vT, K-major), bf16 out
    dim3 gsv(CC / BN, HWN / BM, BB);        // (4, 32, 8)
    tgemm_kernel<6><<<gsv, 256, SMEM_BYTES>>>(
        ps, pqkv + 2 * (size_t)REG_SZ, nullptr, nullptr, po,
        HWN, HWN, CC,
        (size_t)HWN * HWN, (size_t)CC * HWN, (size_t)HWN * CC,
        HWN / KC, 1.f);

    // 6) final projection + bias + residual, transposed -> [b][c][hw] f32
    dim3 gout(CC / BN, Mflat / BM, 1);      // (4, 256)
    tgemm_kernel<3><<<gout, 256, SMEM_BYTES>>>(po, pw + 3 * CC * CC, bo, x, out,
        CC, CC, CC, 0, 0, 0, CC / KC, 1.f);
}

// round 8
// speedup vs baseline: 7.8806x; 1.0252x over previous
#include <cuda_runtime.h>
#include <cuda.h>
#include <cuda_bf16.h>
#include <math.h>
#include <stdint.h>

// Problem constants
#define CC   512
#define HWN  4096
#define BB   8
#define GG   32
#define CPG  16
#define EPSF 1e-6f
#define ALPHAF 0.044194173824159216f

// GEMM tiling (bf16): 128x128 tile, 2 CTAs/SM
#define BM 128
#define BN 128
#define KC 64                          // bf16 elements per K chunk
#define STAGES 3
#define PITCHB  144                    // bytes per smem row (128 data + 16 pad)
#define STG_BYTES ((BM + BN) * PITCHB) // 36864
#define SMEM_BYTES (STAGES * STG_BYTES)  // 110592
#define TRB_PITCH 136                  // bf16 transpose pitch (bf16 units)
#define TRF_PITCH 132                  // f32 transpose pitch (f32 units)

#define REG_SZ (BB * HWN * CC)         // 16M elements per q/k/v region
#define NTILES (HWN / BN)              // 32 n-tiles in scores GEMM

typedef __nv_bfloat16 bf16;
typedef __nv_bfloat162 bf162;

// ---------------------------------------------------------------------------
// Device-global scratch
// ---------------------------------------------------------------------------
__device__ bf16 g_h[BB * HWN * CC];            // normalized [b][n][c]
__device__ bf16 g_qkv[3 * REG_SZ];             // q rowmaj | k rowmaj | vT [b][c][n]
__device__ bf16 g_o[BB * HWN * CC];            // attn out [b][n][c]
__device__ bf16 g_s[(size_t)BB * HWN * HWN];   // unnorm probs exp(s) (256MB)
__device__ bf16 g_w[4 * CC * CC];              // packed weights: wq|wk|wv|wo rows
__device__ float g_bqkv[3 * CC];               // packed biases bq|bk|bv
__device__ float g_psum[(size_t)BB * NTILES * HWN];  // per-tile row sums (4MB)
__device__ float g_mu[BB * GG];
__device__ float g_rstd[BB * GG];

// ---------------------------------------------------------------------------
// Helpers
// ---------------------------------------------------------------------------
__device__ __forceinline__ uint32_t smem_u32(const void* p) {
    uint32_t a;
    asm("{ .reg .u64 t; cvta.to.shared.u64 t, %1; cvt.u32.u64 %0, t; }"
        : "=r"(a) : "l"(p));
    return a;
}
__device__ __forceinline__ void cp_async16(uint32_t dst, const void* src) {
    asm volatile("cp.async.cg.shared.global [%0], [%1], 16;" :: "r"(dst), "l"(src));
}
__device__ __forceinline__ void cp_commit() {
    asm volatile("cp.async.commit_group;");
}
__device__ __forceinline__ void mma_bf16(float* d, const uint32_t* a, const uint32_t* b) {
    asm volatile(
        "mma.sync.aligned.m16n8k16.row.col.f32.bf16.bf16.f32 "
        "{%0,%1,%2,%3},{%4,%5,%6,%7},{%8,%9},{%0,%1,%2,%3};"
        : "+f"(d[0]), "+f"(d[1]), "+f"(d[2]), "+f"(d[3])
        : "r"(a[0]), "r"(a[1]), "r"(a[2]), "r"(a[3]), "r"(b[0]), "r"(b[1]));
}
#define LDSM4(r0, r1, r2, r3, addr) \
    asm volatile("ldmatrix.sync.aligned.m8n8.x4.shared.b16 {%0,%1,%2,%3}, [%4];" \
        : "=r"(r0), "=r"(r1), "=r"(r2), "=r"(r3) : "r"(addr))

__device__ __forceinline__ uint32_t pack2(float x, float y) {
    bf162 h = __floats2bfloat162_rn(x, y);
    return *reinterpret_cast<uint32_t*>(&h);
}

// ---------------------------------------------------------------------------
// bf16 tensor-core GEMM (128x128 tile, 2 CTAs/SM):
//   C[M,N] = A[M,K] * B[N,K]^T  (both K-major bf16)
//  EPI 3: transposed f32 store out[b][ch][tok] = acc + bias + resid (final)
//  EPI 4: fused QKV epilogue (q/k row-major, v transposed; device symbols)
//  EPI 5: scores: store exp(alpha*acc) bf16 + deterministic per-tile row sums
//  EPI 6: SV: store acc * rinv[row] (rinv computed in-epilogue from psum)
// ---------------------------------------------------------------------------
template <int EPI>
__global__ void __launch_bounds__(256, 2)
tgemm_kernel(const bf16* __restrict__ A, const bf16* __restrict__ Bm,
             const float* __restrict__ bias, const float* __restrict__ resid,
             void* __restrict__ Cout_,
             int lda, int ldb, int ldc,
             size_t sA, size_t sB, size_t sC,
             int NC, float alpha)
{
    extern __shared__ char smem[];
    const uint32_t smem_base = smem_u32(smem);
    const int tid = threadIdx.x;
    const int wid = tid >> 5;
    const int lane = tid & 31;
    const int g = lane >> 2;       // groupID 0..7
    const int kin = lane & 3;      // thread-in-group 0..3
    const int wm = wid & 1;        // warp m index (2) -> 64 rows
    const int wn = wid >> 1;       // warp n index (4) -> 32 cols

    const int m0 = blockIdx.y * BM;
    const int n0 = blockIdx.x * BN;
    A  += (size_t)blockIdx.z * sA;
    Bm += (size_t)blockIdx.z * sB;

    // ldmatrix per-thread byte offsets (within a stage)
    const int lq = lane >> 3;      // 0..3 quadrant selector
    const int lr = lane & 7;       // row within matrix
    uint32_t aoff[4], boff[2];
    #pragma unroll
    for (int mt = 0; mt < 4; mt++)
        aoff[mt] = (uint32_t)((wm * 64 + mt * 16 + (lq & 1) * 8 + lr) * PITCHB
                              + (lq >> 1) * 16);
    #pragma unroll
    for (int p = 0; p < 2; p++)
        boff[p] = (uint32_t)(BM * PITCHB
                             + (wn * 32 + (2 * p + (lq >> 1)) * 8 + lr) * PITCHB
                             + (lq & 1) * 16);

    float acc[4][4][4];
    #pragma unroll
    for (int mt = 0; mt < 4; mt++)
        #pragma unroll
        for (int nt = 0; nt < 4; nt++)
            #pragma unroll
            for (int c = 0; c < 4; c++) acc[mt][nt][c] = 0.f;

    // ---- prefetch first STAGES-1 chunks ----
    #pragma unroll
    for (int s = 0; s < STAGES - 1; s++) {
        const int k0 = s * KC;
        const uint32_t sb = smem_base + s * STG_BYTES;
        #pragma unroll
        for (int i = 0; i < 4; i++) {
            int idx = i * 256 + tid;
            int row = idx >> 3, kq = idx & 7;
            cp_async16(sb + row * PITCHB + kq * 16,
                       A + (size_t)(m0 + row) * lda + k0 + kq * 8);
        }
        #pragma unroll
        for (int i = 0; i < 4; i++) {
            int idx = i * 256 + tid;
            int row = idx >> 3, kq = idx & 7;
            cp_async16(sb + BM * PITCHB + row * PITCHB + kq * 16,
                       Bm + (size_t)(n0 + row) * ldb + k0 + kq * 8);
        }
        cp_commit();
    }

    // ---- main loop ----
    for (int c = 0; c < NC; c++) {
        asm volatile("cp.async.wait_group %0;" :: "n"(STAGES - 2));
        __syncthreads();

        const int pf = c + STAGES - 1;
        if (pf < NC) {
            const int k0 = pf * KC;
            const uint32_t sb = smem_base + (pf % STAGES) * STG_BYTES;
            #pragma unroll
            for (int i = 0; i < 4; i++) {
                int idx = i * 256 + tid;
                int row = idx >> 3, kq = idx & 7;
                cp_async16(sb + row * PITCHB + kq * 16,
                           A + (size_t)(m0 + row) * lda + k0 + kq * 8);
            }
            #pragma unroll
            for (int i = 0; i < 4; i++) {
                int idx = i * 256 + tid;
                int row = idx >> 3, kq = idx & 7;
                cp_async16(sb + BM * PITCHB + row * PITCHB + kq * 16,
                           Bm + (size_t)(n0 + row) * ldb + k0 + kq * 8);
            }
            cp_commit();
        }

        const uint32_t sb = smem_base + (c % STAGES) * STG_BYTES;
        #pragma unroll
        for (int ks = 0; ks < 4; ks++) {           // 4 x k16 per KC=64
            const uint32_t kb = sb + ks * 32;
            uint32_t af[4][4];
            #pragma unroll
            for (int mt = 0; mt < 4; mt++)
                LDSM4(af[mt][0], af[mt][1], af[mt][2], af[mt][3], kb + aoff[mt]);
            uint32_t bf[4][2];
            #pragma unroll
            for (int p = 0; p < 2; p++)
                LDSM4(bf[2 * p][0], bf[2 * p][1], bf[2 * p + 1][0], bf[2 * p + 1][1],
                      kb + boff[p]);
            #pragma unroll
            for (int mt = 0; mt < 4; mt++)
                #pragma unroll
                for (int nt = 0; nt < 4; nt++)
                    mma_bf16(acc[mt][nt], af[mt], bf[nt]);
        }
    }

    // ---- epilogue ----
    if (EPI == 5) {
        // scores: P = exp(alpha*acc) bf16 + per-tile row sums (deterministic)
        bf16* Cout = (bf16*)Cout_ + (size_t)blockIdx.z * sC;
        __syncthreads();
        float (*sm)[5] = (float(*)[5])smem;   // [128][5] pad -> conflict-free
        #pragma unroll
        for (int mt = 0; mt < 4; mt++) {
            int rl = wm * 64 + mt * 16 + g;
            int r0 = m0 + rl;
            float s0 = 0.f, s1 = 0.f;
            #pragma unroll
            for (int nt = 0; nt < 4; nt++) {
                int ch = n0 + wn * 32 + nt * 8 + kin * 2;
                float e0 = __expf(alpha * acc[mt][nt][0]);
                float e1 = __expf(alpha * acc[mt][nt][1]);
                float e2 = __expf(alpha * acc[mt][nt][2]);
                float e3 = __expf(alpha * acc[mt][nt][3]);
                *(bf162*)(Cout + (size_t)r0 * ldc + ch) = __floats2bfloat162_rn(e0, e1);
                *(bf162*)(Cout + (size_t)(r0 + 8) * ldc + ch) = __floats2bfloat162_rn(e2, e3);
                s0 += e0 + e1;
                s1 += e2 + e3;
            }
            s0 += __shfl_xor_sync(0xffffffffu, s0, 1);
            s0 += __shfl_xor_sync(0xffffffffu, s0, 2);
            s1 += __shfl_xor_sync(0xffffffffu, s1, 1);
            s1 += __shfl_xor_sync(0xffffffffu, s1, 2);
            if (kin == 0) {
                sm[rl][wn] = s0;
                sm[rl + 8][wn] = s1;
            }
        }
        __syncthreads();
        if (tid < 128) {
            float t = sm[tid][0] + sm[tid][1] + sm[tid][2] + sm[tid][3];
            g_psum[((size_t)blockIdx.z * NTILES + blockIdx.x) * HWN + m0 + tid] = t;
        }
    } else if (EPI == 6) {
        // SV: compute rinv for this CTA's 128 rows from psum, then normalize
        bf16* Cout = (bf16*)Cout_ + (size_t)blockIdx.z * sC;
        __syncthreads();
        float* rsh = (float*)smem;
        if (tid < 128) {
            const float* p = g_psum + (size_t)blockIdx.z * NTILES * HWN + m0 + tid;
            float s = 0.f;
            #pragma unroll
            for (int t = 0; t < NTILES; t++) s += p[(size_t)t * HWN];
            rsh[tid] = 1.f / s;
        }
        __syncthreads();
        #pragma unroll
        for (int mt = 0; mt < 4; mt++) {
            int rl = wm * 64 + mt * 16 + g;
            int r0 = m0 + rl;
            float i0 = rsh[rl], i1 = rsh[rl + 8];
            #pragma unroll
            for (int nt = 0; nt < 4; nt++) {
                int ch = n0 + wn * 32 + nt * 8 + kin * 2;
                *(bf162*)(Cout + (size_t)r0 * ldc + ch) =
                    __floats2bfloat162_rn(acc[mt][nt][0] * i0, acc[mt][nt][1] * i0);
                *(bf162*)(Cout + (size_t)(r0 + 8) * ldc + ch) =
                    __floats2bfloat162_rn(acc[mt][nt][2] * i1, acc[mt][nt][3] * i1);
            }
        }
    } else if (EPI == 4) {
        // fused QKV epilogue; n0 in [0, 1536), tiles of 128
        const int which = n0 >> 9;            // 0=q, 1=k, 2=v
        if (which < 2) {
            bf16* Cout = g_qkv + (size_t)which * REG_SZ;
            const int nsub0 = n0 & 511;
            #pragma unroll
            for (int mt = 0; mt < 4; mt++) {
                int r0 = m0 + wm * 64 + mt * 16 + g;
                #pragma unroll
                for (int nt = 0; nt < 4; nt++) {
                    int cl = wn * 32 + nt * 8 + kin * 2;
                    float b0 = g_bqkv[n0 + cl], b1 = g_bqkv[n0 + cl + 1];
                    int ch = nsub0 + cl;
                    *(bf162*)(Cout + (size_t)r0 * CC + ch) =
                        __floats2bfloat162_rn(acc[mt][nt][0] + b0, acc[mt][nt][1] + b1);
                    *(bf162*)(Cout + (size_t)(r0 + 8) * CC + ch) =
                        __floats2bfloat162_rn(acc[mt][nt][2] + b0, acc[mt][nt][3] + b1);
                }
            }
        } else {
            // v: transposed bf16 store via smem, out layout [b][c][n]
            bf16* Cout = g_qkv + 2 * (size_t)REG_SZ;
            __syncthreads();
            bf16* tr = (bf16*)smem;
            #pragma unroll
            for (int mt = 0; mt < 4; mt++) {
                int tok = wm * 64 + mt * 16 + g;
                #pragma unroll
                for (int nt = 0; nt < 4; nt++) {
                    int cl = wn * 32 + nt * 8 + kin * 2;
                    float b0 = g_bqkv[n0 + cl], b1 = g_bqkv[n0 + cl + 1];
                    tr[(cl    ) * TRB_PITCH + tok    ] = __float2bfloat16_rn(acc[mt][nt][0] + b0);
                    tr[(cl + 1) * TRB_PITCH + tok    ] = __float2bfloat16_rn(acc[mt][nt][1] + b1);
                    tr[(cl    ) * TRB_PITCH + tok + 8] = __float2bfloat16_rn(acc[mt][nt][2] + b0);
                    tr[(cl + 1) * TRB_PITCH + tok + 8] = __float2bfloat16_rn(acc[mt][nt][3] + b1);
                }
            }
            __syncthreads();
            const int bidx = m0 >> 12;
            const int tok0 = m0 & 4095;
            const int vch0 = n0 - 1024;       // 0,128,256,384
            #pragma unroll
            for (int i = 0; i < 8; i++) {
                int idx = i * 256 + tid;
                int cl = idx >> 4, t8 = (idx & 15) * 8;
                uint4 v = *(uint4*)&tr[cl * TRB_PITCH + t8];
                *(uint4*)(Cout + ((size_t)bidx * CC + vch0 + cl) * HWN + tok0 + t8) = v;
            }
        }
    } else {
        // EPI 3: f32 transposed store + bias + residual
        float* Cout = (float*)Cout_ + (size_t)blockIdx.z * sC;
        __syncthreads();
        float* tr = (float*)smem;
        #pragma unroll
        for (int mt = 0; mt < 4; mt++) {
            int tok = wm * 64 + mt * 16 + g;
            #pragma unroll
            for (int nt = 0; nt < 4; nt++) {
                int ch = wn * 32 + nt * 8 + kin * 2;
                tr[(ch    ) * TRF_PITCH + tok    ] = acc[mt][nt][0];
                tr[(ch + 1) * TRF_PITCH + tok    ] = acc[mt][nt][1];
                tr[(ch    ) * TRF_PITCH + tok + 8] = acc[mt][nt][2];
                tr[(ch + 1) * TRF_PITCH + tok + 8] = acc[mt][nt][3];
            }
        }
        __syncthreads();
        const int bidx = m0 >> 12;
        const int tok0 = m0 & 4095;
        #pragma unroll
        for (int i = 0; i < 16; i++) {
            int idx = i * 256 + tid;
            int ch = idx >> 5, t4 = (idx & 31) * 4;
            float4 v = *(float4*)&tr[ch * TRF_PITCH + t4];
            float bv = bias[n0 + ch];
            v.x += bv; v.y += bv; v.z += bv; v.w += bv;
            size_t oidx = ((size_t)bidx * CC + n0 + ch) * HWN + tok0 + t4;
            float4 rr = *(const float4*)(resid + oidx);
            v.x += rr.x; v.y += rr.y; v.z += rr.z; v.w += rr.w;
            *(float4*)(Cout + oidx) = v;
        }
    }
}

// ---------------------------------------------------------------------------
// Round ALL weights to bf16 in one launch (wq|wk|wv|wo -> g_w packed)
// ---------------------------------------------------------------------------
__global__ void round_w_all_kernel(const float* __restrict__ wq,
                                   const float* __restrict__ wk,
                                   const float* __restrict__ wv,
                                   const float* __restrict__ wo) {
    int i = (blockIdx.x * 256 + threadIdx.x) * 4;   // 0..4*CC*CC-1
    int w = i >> 18;                                // CC*CC = 262144 = 2^18
    const float* s = (w == 0) ? wq : (w == 1) ? wk : (w == 2) ? wv : wo;
    float4 v = *(const float4*)(s + (i & (CC * CC - 1)));
    uint2 o;
    o.x = pack2(v.x, v.y);
    o.y = pack2(v.z, v.w);
    *(uint2*)(g_w + i) = o;
}

// Pack q/k/v biases into g_bqkv
__global__ void bias_pack_kernel(const float* __restrict__ bq,
                                 const float* __restrict__ bk,
                                 const float* __restrict__ bv) {
    int i = blockIdx.x * 256 + threadIdx.x;   // 0..1535
    const float* src = (i < CC) ? bq : (i < 2 * CC) ? bk : bv;
    g_bqkv[i] = src[i & (CC - 1)];
}

// ---------------------------------------------------------------------------
// GroupNorm stats (vectorized)
// ---------------------------------------------------------------------------
__global__ void gn_stats_kernel(const float* __restrict__ x) {
    const int bg = blockIdx.x;
    const int b = bg / GG, g = bg % GG;
    const float4* xp = (const float4*)(x + ((size_t)b * CC + (size_t)g * CPG) * HWN);
    float s = 0.f, ss = 0.f;
    #pragma unroll 4
    for (int i = threadIdx.x; i < CPG * HWN / 4; i += 256) {
        float4 v = xp[i];
        s  += v.x + v.y + v.z + v.w;
        ss += v.x * v.x + v.y * v.y + v.z * v.z + v.w * v.w;
    }
    __shared__ float sh1[256], sh2[256];
    sh1[threadIdx.x] = s; sh2[threadIdx.x] = ss;
    __syncthreads();
    for (int o = 128; o > 0; o >>= 1) {
        if (threadIdx.x < o) {
            sh1[threadIdx.x] += sh1[threadIdx.x + o];
            sh2[threadIdx.x] += sh2[threadIdx.x + o];
        }
        __syncthreads();
    }
    if (threadIdx.x == 0) {
        const float inv_n = 1.f / (CPG * HWN);
        float mu = sh1[0] * inv_n;
        float var = sh2[0] * inv_n - mu * mu;
        g_mu[bg] = mu;
        g_rstd[bg] = rsqrtf(var + EPSF);
    }
}

// ---------------------------------------------------------------------------
// Normalize + transpose -> h[b][n][c] bf16
// ---------------------------------------------------------------------------
__global__ void gn_norm_t_kernel(const float* __restrict__ x,
                                 const float* __restrict__ gamma,
                                 const float* __restrict__ beta) {
    __shared__ float tile[32][33];
    const int b = blockIdx.z;
    const int n0 = blockIdx.x * 32;
    const int c0 = blockIdx.y * 32;
    #pragma unroll
    for (int i = 0; i < 4; i++) {
        int c = c0 + threadIdx.y + i * 8;
        int n = n0 + threadIdx.x;
        float v = x[((size_t)b * CC + c) * HWN + n];
        int gidx = b * GG + (c / CPG);
        v = (v - g_mu[gidx]) * g_rstd[gidx] * gamma[c] + beta[c];
        tile[threadIdx.y + i * 8][threadIdx.x] = v;
    }
    __syncthreads();
    #pragma unroll
    for (int i = 0; i < 4; i++) {
        int n = n0 + threadIdx.y + i * 8;
        int c = c0 + threadIdx.x;
        g_h[((size_t)b * HWN + n) * CC + c] =
            __float2bfloat16_rn(tile[threadIdx.x][threadIdx.y + i * 8]);
    }
}

// ---------------------------------------------------------------------------
// Launch
// ---------------------------------------------------------------------------
extern "C" void kernel_launch(void* const* d_in, const int* in_sizes, int n_in,
                              void* d_out, int out_size) {
    const float* x     = (const float*)d_in[0];
    const float* gamma = (const float*)d_in[1];
    const float* beta  = (const float*)d_in[2];
    const float* wq    = (const float*)d_in[3];
    const float* bq    = (const float*)d_in[4];
    const float* wk    = (const float*)d_in[5];
    const float* bk    = (const float*)d_in[6];
    const float* wv    = (const float*)d_in[7];
    const float* bv    = (const float*)d_in[8];
    const float* wo    = (const float*)d_in[9];
    const float* bo    = (const float*)d_in[10];
    float* out = (float*)d_out;

    bf16 *ph, *pqkv, *po, *ps, *pw;
    cudaGetSymbolAddress((void**)&ph, g_h);
    cudaGetSymbolAddress((void**)&pqkv, g_qkv);
    cudaGetSymbolAddress((void**)&po, g_o);
    cudaGetSymbolAddress((void**)&ps, g_s);
    cudaGetSymbolAddress((void**)&pw, g_w);

    cudaFuncSetAttribute(tgemm_kernel<3>, cudaFuncAttributeMaxDynamicSharedMemorySize, SMEM_BYTES);
    cudaFuncSetAttribute(tgemm_kernel<4>, cudaFuncAttributeMaxDynamicSharedMemorySize, SMEM_BYTES);
    cudaFuncSetAttribute(tgemm_kernel<5>, cudaFuncAttributeMaxDynamicSharedMemorySize, SMEM_BYTES);
    cudaFuncSetAttribute(tgemm_kernel<6>, cudaFuncAttributeMaxDynamicSharedMemorySize, SMEM_BYTES);

    // 0) weights -> bf16 packed (single launch), biases packed
    round_w_all_kernel<<<4 * CC * CC / (256 * 4), 256>>>(wq, wk, wv, wo);
    bias_pack_kernel<<<6, 256>>>(bq, bk, bv);

    // 1) GroupNorm
    gn_stats_kernel<<<BB * GG, 256>>>(x);
    gn_norm_t_kernel<<<dim3(HWN / 32, CC / 32, BB), dim3(32, 8)>>>(x, gamma, beta);

    const int Mflat = BB * HWN;

    // 2) fused QKV projection: [32768, 1536] = h @ [wq|wk|wv]^T
    dim3 gqkv(3 * CC / BN, Mflat / BM, 1);  // (12, 256)
    tgemm_kernel<4><<<gqkv, 256, SMEM_BYTES>>>(ph, pw, nullptr, nullptr, nullptr,
        CC, CC, 0, 0, 0, 0, CC / KC, 1.f);

    // 3) scores + exp + row-sum partials: P = exp(alpha * Q K^T)
    dim3 gscore(HWN / BN, HWN / BM, BB);    // (32, 32, 8)
    tgemm_kernel<5><<<gscore, 256, SMEM_BYTES>>>(
        pqkv, pqkv + REG_SZ, nullptr, nullptr, ps,
        CC, CC, HWN,
        (size_t)HWN * CC, (size_t)HWN * CC, (size_t)HWN * HWN,
        CC / KC, ALPHAF);

    // 4) O[b] = (P[b] @ V[b]) * rinv  (rinv computed in epilogue from psum)
    dim3 gsv(CC / BN, HWN / BM, BB);        // (4, 32, 8)
    tgemm_kernel<6><<<gsv, 256, SMEM_BYTES>>>(
        ps, pqkv + 2 * (size_t)REG_SZ, nullptr, nullptr, po,
        HWN, HWN, CC,
        (size_t)HWN * HWN, (size_t)CC * HWN, (size_t)HWN * CC,
        HWN / KC, 1.f);

    // 5) final projection + bias + residual, transposed -> [b][c][hw] f32
    dim3 gout(CC / BN, Mflat / BM, 1);      // (4, 256)
    tgemm_kernel<3><<<gout, 256, SMEM_BYTES>>>(po, pw + 3 * CC * CC, bo, x, out,
        CC, CC, CC, 0, 0, 0, CC / KC, 1.f);
}

// round 9
// speedup vs baseline: 8.0071x; 1.0161x over previous
#include <cuda_runtime.h>
#include <cuda.h>
#include <cuda_bf16.h>
#include <math.h>
#include <stdint.h>

// Problem constants
#define CC   512
#define HWN  4096
#define BB   8
#define GG   32
#define CPG  16
#define EPSF 1e-6f
#define ALPHAF 0.044194173824159216f
#define ALPHA_LOG2E 0.06376059f        // ALPHAF * log2(e)

// GEMM tiling (bf16): 128x128 tile, 2 CTAs/SM
#define BM 128
#define BN 128
#define KC 64                          // bf16 elements per K chunk
#define STAGES 3
#define PITCHB  144                    // bytes per smem row (128 data + 16 pad)
#define STG_BYTES ((BM + BN) * PITCHB) // 36864
#define SMEM_BYTES (STAGES * STG_BYTES)  // 110592
#define TRB_PITCH 136                  // bf16 transpose pitch (bf16 units)
#define TRF_PITCH 132                  // f32 transpose pitch (f32 units)

#define REG_SZ (BB * HWN * CC)         // 16M elements per q/k/v region
#define NTILES (HWN / BN)              // 32 n-tiles in scores GEMM

typedef __nv_bfloat16 bf16;
typedef __nv_bfloat162 bf162;

// ---------------------------------------------------------------------------
// Device-global scratch
// ---------------------------------------------------------------------------
__device__ bf16 g_h[BB * HWN * CC];            // normalized [b][n][c]
__device__ bf16 g_qkv[3 * REG_SZ];             // q | k | v, all row-major [b][n][c]
__device__ bf16 g_vpt[REG_SZ];                 // V' = V@Wo^T, transposed [b][c][n]
__device__ bf16 g_s[(size_t)BB * HWN * HWN];   // unnorm probs exp(s) (256MB)
__device__ bf16 g_w[4 * CC * CC];              // packed weights: wq|wk|wv|wo rows
__device__ float g_bqkv[3 * CC];               // packed biases bq|bk|bv
__device__ float g_psum[(size_t)BB * NTILES * HWN];  // per-tile row sums (4MB)
__device__ float g_mu[BB * GG];
__device__ float g_rstd[BB * GG];

// ---------------------------------------------------------------------------
// Helpers
// ---------------------------------------------------------------------------
__device__ __forceinline__ uint32_t smem_u32(const void* p) {
    uint32_t a;
    asm("{ .reg .u64 t; cvta.to.shared.u64 t, %1; cvt.u32.u64 %0, t; }"
        : "=r"(a) : "l"(p));
    return a;
}
__device__ __forceinline__ void cp_async16(uint32_t dst, const void* src) {
    asm volatile("cp.async.cg.shared.global [%0], [%1], 16;" :: "r"(dst), "l"(src));
}
__device__ __forceinline__ void cp_commit() {
    asm volatile("cp.async.commit_group;");
}
__device__ __forceinline__ void mma_bf16(float* d, const uint32_t* a, const uint32_t* b) {
    asm volatile(
        "mma.sync.aligned.m16n8k16.row.col.f32.bf16.bf16.f32 "
        "{%0,%1,%2,%3},{%4,%5,%6,%7},{%8,%9},{%0,%1,%2,%3};"
        : "+f"(d[0]), "+f"(d[1]), "+f"(d[2]), "+f"(d[3])
        : "r"(a[0]), "r"(a[1]), "r"(a[2]), "r"(a[3]), "r"(b[0]), "r"(b[1]));
}
#define LDSM4(r0, r1, r2, r3, addr) \
    asm volatile("ldmatrix.sync.aligned.m8n8.x4.shared.b16 {%0,%1,%2,%3}, [%4];" \
        : "=r"(r0), "=r"(r1), "=r"(r2), "=r"(r3) : "r"(addr))

__device__ __forceinline__ uint32_t pack2(float x, float y) {
    bf162 h = __floats2bfloat162_rn(x, y);
    return *reinterpret_cast<uint32_t*>(&h);
}

// ---------------------------------------------------------------------------
// bf16 tensor-core GEMM (128x128 tile, 2 CTAs/SM):
//   C[M,N] = A[M,K] * B[N,K]^T  (both K-major bf16)
//  EPI 2: V' GEMM: transposed bf16 store g_vpt[b][ch][tok] (no bias)
//  EPI 4: fused QKV epilogue (q/k/v all row-major + bias)
//  EPI 5: scores: store exp2(alpha*acc) bf16 + deterministic per-tile row sums
//  EPI 7: SV final: acc*rinv + bo[ch] + resid, transposed f32 store to out
// ---------------------------------------------------------------------------
template <int EPI>
__global__ void __launch_bounds__(256, 2)
tgemm_kernel(const bf16* __restrict__ A, const bf16* __restrict__ Bm,
             const float* __restrict__ bias, const float* __restrict__ resid,
             void* __restrict__ Cout_,
             int lda, int ldb, int ldc,
             size_t sA, size_t sB, size_t sC,
             int NC, float alpha)
{
    extern __shared__ char smem[];
    const uint32_t smem_base = smem_u32(smem);
    const int tid = threadIdx.x;
    const int wid = tid >> 5;
    const int lane = tid & 31;
    const int g = lane >> 2;       // groupID 0..7
    const int kin = lane & 3;      // thread-in-group 0..3
    const int wm = wid & 1;        // warp m index (2) -> 64 rows
    const int wn = wid >> 1;       // warp n index (4) -> 32 cols

    const int m0 = blockIdx.y * BM;
    const int n0 = blockIdx.x * BN;
    A  += (size_t)blockIdx.z * sA;
    Bm += (size_t)blockIdx.z * sB;

    // ldmatrix per-thread byte offsets (within a stage)
    const int lq = lane >> 3;      // 0..3 quadrant selector
    const int lr = lane & 7;       // row within matrix
    uint32_t aoff[4], boff[2];
    #pragma unroll
    for (int mt = 0; mt < 4; mt++)
        aoff[mt] = (uint32_t)((wm * 64 + mt * 16 + (lq & 1) * 8 + lr) * PITCHB
                              + (lq >> 1) * 16);
    #pragma unroll
    for (int p = 0; p < 2; p++)
        boff[p] = (uint32_t)(BM * PITCHB
                             + (wn * 32 + (2 * p + (lq >> 1)) * 8 + lr) * PITCHB
                             + (lq & 1) * 16);

    float acc[4][4][4];
    #pragma unroll
    for (int mt = 0; mt < 4; mt++)
        #pragma unroll
        for (int nt = 0; nt < 4; nt++)
            #pragma unroll
            for (int c = 0; c < 4; c++) acc[mt][nt][c] = 0.f;

    // ---- prefetch first STAGES-1 chunks ----
    #pragma unroll
    for (int s = 0; s < STAGES - 1; s++) {
        const int k0 = s * KC;
        const uint32_t sb = smem_base + s * STG_BYTES;
        #pragma unroll
        for (int i = 0; i < 4; i++) {
            int idx = i * 256 + tid;
            int row = idx >> 3, kq = idx & 7;
            cp_async16(sb + row * PITCHB + kq * 16,
                       A + (size_t)(m0 + row) * lda + k0 + kq * 8);
        }
        #pragma unroll
        for (int i = 0; i < 4; i++) {
            int idx = i * 256 + tid;
            int row = idx >> 3, kq = idx & 7;
            cp_async16(sb + BM * PITCHB + row * PITCHB + kq * 16,
                       Bm + (size_t)(n0 + row) * ldb + k0 + kq * 8);
        }
        cp_commit();
    }

    // ---- main loop ----
    for (int c = 0; c < NC; c++) {
        asm volatile("cp.async.wait_group %0;" :: "n"(STAGES - 2));
        __syncthreads();

        const int pf = c + STAGES - 1;
        if (pf < NC) {
            const int k0 = pf * KC;
            const uint32_t sb = smem_base + (pf % STAGES) * STG_BYTES;
            #pragma unroll
            for (int i = 0; i < 4; i++) {
                int idx = i * 256 + tid;
                int row = idx >> 3, kq = idx & 7;
                cp_async16(sb + row * PITCHB + kq * 16,
                           A + (size_t)(m0 + row) * lda + k0 + kq * 8);
            }
            #pragma unroll
            for (int i = 0; i < 4; i++) {
                int idx = i * 256 + tid;
                int row = idx >> 3, kq = idx & 7;
                cp_async16(sb + BM * PITCHB + row * PITCHB + kq * 16,
                           Bm + (size_t)(n0 + row) * ldb + k0 + kq * 8);
            }
            cp_commit();
        }

        const uint32_t sb = smem_base + (c % STAGES) * STG_BYTES;
        #pragma unroll
        for (int ks = 0; ks < 4; ks++) {           // 4 x k16 per KC=64
            const uint32_t kb = sb + ks * 32;
            uint32_t af[4][4];
            #pragma unroll
            for (int mt = 0; mt < 4; mt++)
                LDSM4(af[mt][0], af[mt][1], af[mt][2], af[mt][3], kb + aoff[mt]);
            uint32_t bf[4][2];
            #pragma unroll
            for (int p = 0; p < 2; p++)
                LDSM4(bf[2 * p][0], bf[2 * p][1], bf[2 * p + 1][0], bf[2 * p + 1][1],
                      kb + boff[p]);
            #pragma unroll
            for (int mt = 0; mt < 4; mt++)
                #pragma unroll
                for (int nt = 0; nt < 4; nt++)
                    mma_bf16(acc[mt][nt], af[mt], bf[nt]);
        }
    }

    // ---- epilogue ----
    if (EPI == 5) {
        // scores: P = exp2(alpha*acc) bf16 + per-tile row sums (deterministic)
        bf16* Cout = (bf16*)Cout_ + (size_t)blockIdx.z * sC;
        __syncthreads();
        float (*sm)[5] = (float(*)[5])smem;   // [128][5] pad -> conflict-free
        #pragma unroll
        for (int mt = 0; mt < 4; mt++) {
            int rl = wm * 64 + mt * 16 + g;
            int r0 = m0 + rl;
            float s0 = 0.f, s1 = 0.f;
            #pragma unroll
            for (int nt = 0; nt < 4; nt++) {
                int ch = n0 + wn * 32 + nt * 8 + kin * 2;
                float e0 = exp2f(alpha * acc[mt][nt][0]);
                float e1 = exp2f(alpha * acc[mt][nt][1]);
                float e2 = exp2f(alpha * acc[mt][nt][2]);
                float e3 = exp2f(alpha * acc[mt][nt][3]);
                *(bf162*)(Cout + (size_t)r0 * ldc + ch) = __floats2bfloat162_rn(e0, e1);
                *(bf162*)(Cout + (size_t)(r0 + 8) * ldc + ch) = __floats2bfloat162_rn(e2, e3);
                s0 += e0 + e1;
                s1 += e2 + e3;
            }
            s0 += __shfl_xor_sync(0xffffffffu, s0, 1);
            s0 += __shfl_xor_sync(0xffffffffu, s0, 2);
            s1 += __shfl_xor_sync(0xffffffffu, s1, 1);
            s1 += __shfl_xor_sync(0xffffffffu, s1, 2);
            if (kin == 0) {
                sm[rl][wn] = s0;
                sm[rl + 8][wn] = s1;
            }
        }
        __syncthreads();
        if (tid < 128) {
            float t = sm[tid][0] + sm[tid][1] + sm[tid][2] + sm[tid][3];
            g_psum[((size_t)blockIdx.z * NTILES + blockIdx.x) * HWN + m0 + tid] = t;
        }
    } else if (EPI == 7) {
        // SV final: rinv from psum, scale, + bo + resid, transposed f32 out
        float* Cout = (float*)Cout_;
        __syncthreads();
        float* rsh = (float*)smem;
        if (tid < 128) {
            const float* p = g_psum + (size_t)blockIdx.z * NTILES * HWN + m0 + tid;
            float s = 0.f;
            #pragma unroll
            for (int t = 0; t < NTILES; t++) s += p[(size_t)t * HWN];
            rsh[tid] = 1.f / s;
        }
        __syncthreads();
        float iv[4][2];
        #pragma unroll
        for (int mt = 0; mt < 4; mt++) {
            int rl = wm * 64 + mt * 16 + g;
            iv[mt][0] = rsh[rl];
            iv[mt][1] = rsh[rl + 8];
        }
        __syncthreads();
        float* tr = (float*)smem;
        #pragma unroll
        for (int mt = 0; mt < 4; mt++) {
            int tok = wm * 64 + mt * 16 + g;
            #pragma unroll
            for (int nt = 0; nt < 4; nt++) {
                int ch = wn * 32 + nt * 8 + kin * 2;
                tr[(ch    ) * TRF_PITCH + tok    ] = acc[mt][nt][0] * iv[mt][0];
                tr[(ch + 1) * TRF_PITCH + tok    ] = acc[mt][nt][1] * iv[mt][0];
                tr[(ch    ) * TRF_PITCH + tok + 8] = acc[mt][nt][2] * iv[mt][1];
                tr[(ch + 1) * TRF_PITCH + tok + 8] = acc[mt][nt][3] * iv[mt][1];
            }
        }
        __syncthreads();
        const int bidx = blockIdx.z;
        const int tok0 = m0;
        #pragma unroll
        for (int i = 0; i < 16; i++) {
            int idx = i * 256 + tid;
            int ch = idx >> 5, t4 = (idx & 31) * 4;
            float4 v = *(float4*)&tr[ch * TRF_PITCH + t4];
            float bv = bias[n0 + ch];
            v.x += bv; v.y += bv; v.z += bv; v.w += bv;
            size_t oidx = ((size_t)bidx * CC + n0 + ch) * HWN + tok0 + t4;
            float4 rr = *(const float4*)(resid + oidx);
            v.x += rr.x; v.y += rr.y; v.z += rr.z; v.w += rr.w;
            *(float4*)(Cout + oidx) = v;
        }
    } else if (EPI == 4) {
        // fused QKV epilogue; n0 in [0, 1536); all row-major
        const int which = n0 >> 9;            // 0=q, 1=k, 2=v
        bf16* Cout = g_qkv + (size_t)which * REG_SZ;
        const int nsub0 = n0 & 511;
        #pragma unroll
        for (int mt = 0; mt < 4; mt++) {
            int r0 = m0 + wm * 64 + mt * 16 + g;
            #pragma unroll
            for (int nt = 0; nt < 4; nt++) {
                int cl = wn * 32 + nt * 8 + kin * 2;
                float b0 = g_bqkv[n0 + cl], b1 = g_bqkv[n0 + cl + 1];
                int ch = nsub0 + cl;
                *(bf162*)(Cout + (size_t)r0 * CC + ch) =
                    __floats2bfloat162_rn(acc[mt][nt][0] + b0, acc[mt][nt][1] + b1);
                *(bf162*)(Cout + (size_t)(r0 + 8) * CC + ch) =
                    __floats2bfloat162_rn(acc[mt][nt][2] + b0, acc[mt][nt][3] + b1);
            }
        }
    } else {
        // EPI 2: V' transposed bf16 store -> g_vpt[b][ch][tok] (no bias)
        __syncthreads();
        bf16* tr = (bf16*)smem;
        #pragma unroll
        for (int mt = 0; mt < 4; mt++) {
            int tok = wm * 64 + mt * 16 + g;
            #pragma unroll
            for (int nt = 0; nt < 4; nt++) {
                int cl = wn * 32 + nt * 8 + kin * 2;
                tr[(cl    ) * TRB_PITCH + tok    ] = __float2bfloat16_rn(acc[mt][nt][0]);
                tr[(cl + 1) * TRB_PITCH + tok    ] = __float2bfloat16_rn(acc[mt][nt][1]);
                tr[(cl    ) * TRB_PITCH + tok + 8] = __float2bfloat16_rn(acc[mt][nt][2]);
                tr[(cl + 1) * TRB_PITCH + tok + 8] = __float2bfloat16_rn(acc[mt][nt][3]);
            }
        }
        __syncthreads();
        const int bidx = m0 >> 12;
        const int tok0 = m0 & 4095;
        #pragma unroll
        for (int i = 0; i < 8; i++) {
            int idx = i * 256 + tid;
            int cl = idx >> 4, t8 = (idx & 15) * 8;
            uint4 v = *(uint4*)&tr[cl * TRB_PITCH + t8];
            *(uint4*)(g_vpt + ((size_t)bidx * CC + n0 + cl) * HWN + tok0 + t8) = v;
        }
    }
}

// ---------------------------------------------------------------------------
// Prep kernel: weights->bf16 (blocks 0..1023), biases (1024..1029),
// GN stats (1030..1285)
// ---------------------------------------------------------------------------
__global__ void prep_kernel(const float* __restrict__ wq, const float* __restrict__ wk,
                            const float* __restrict__ wv, const float* __restrict__ wo,
                            const float* __restrict__ bq, const float* __restrict__ bk,
                            const float* __restrict__ bv, const float* __restrict__ x) {
    __shared__ float sh1[256], sh2[256];
    const int blk = blockIdx.x;
    if (blk < 1024) {
        int i = (blk * 256 + threadIdx.x) * 4;
        int w = i >> 18;
        const float* s = (w == 0) ? wq : (w == 1) ? wk : (w == 2) ? wv : wo;
        float4 v = *(const float4*)(s + (i & (CC * CC - 1)));
        uint2 o;
        o.x = pack2(v.x, v.y);
        o.y = pack2(v.z, v.w);
        *(uint2*)(g_w + i) = o;
    } else if (blk < 1030) {
        int i = (blk - 1024) * 256 + threadIdx.x;
        const float* src = (i < CC) ? bq : (i < 2 * CC) ? bk : bv;
        g_bqkv[i] = src[i & (CC - 1)];
    } else {
        const int bg = blk - 1030;
        const int b = bg / GG, g = bg % GG;
        const float4* xp = (const float4*)(x + ((size_t)b * CC + (size_t)g * CPG) * HWN);
        float s = 0.f, ss = 0.f;
        #pragma unroll 4
        for (int i = threadIdx.x; i < CPG * HWN / 4; i += 256) {
            float4 v = xp[i];
            s  += v.x + v.y + v.z + v.w;
            ss += v.x * v.x + v.y * v.y + v.z * v.z + v.w * v.w;
        }
        sh1[threadIdx.x] = s; sh2[threadIdx.x] = ss;
        __syncthreads();
        for (int o = 128; o > 0; o >>= 1) {
            if (threadIdx.x < o) {
                sh1[threadIdx.x] += sh1[threadIdx.x + o];
                sh2[threadIdx.x] += sh2[threadIdx.x + o];
            }
            __syncthreads();
        }
        if (threadIdx.x == 0) {
            const float inv_n = 1.f / (CPG * HWN);
            float mu = sh1[0] * inv_n;
            float var = sh2[0] * inv_n - mu * mu;
            g_mu[bg] = mu;
            g_rstd[bg] = rsqrtf(var + EPSF);
        }
    }
}

// ---------------------------------------------------------------------------
// Normalize + transpose -> h[b][n][c] bf16
// ---------------------------------------------------------------------------
__global__ void gn_norm_t_kernel(const float* __restrict__ x,
                                 const float* __restrict__ gamma,
                                 const float* __restrict__ beta) {
    __shared__ float tile[32][33];
    const int b = blockIdx.z;
    const int n0 = blockIdx.x * 32;
    const int c0 = blockIdx.y * 32;
    #pragma unroll
    for (int i = 0; i < 4; i++) {
        int c = c0 + threadIdx.y + i * 8;
        int n = n0 + threadIdx.x;
        float v = x[((size_t)b * CC + c) * HWN + n];
        int gidx = b * GG + (c / CPG);
        v = (v - g_mu[gidx]) * g_rstd[gidx] * gamma[c] + beta[c];
        tile[threadIdx.y + i * 8][threadIdx.x] = v;
    }
    __syncthreads();
    #pragma unroll
    for (int i = 0; i < 4; i++) {
        int n = n0 + threadIdx.y + i * 8;
        int c = c0 + threadIdx.x;
        g_h[((size_t)b * HWN + n) * CC + c] =
            __float2bfloat16_rn(tile[threadIdx.x][threadIdx.y + i * 8]);
    }
}

// ---------------------------------------------------------------------------
// Launch
// ---------------------------------------------------------------------------
extern "C" void kernel_launch(void* const* d_in, const int* in_sizes, int n_in,
                              void* d_out, int out_size) {
    const float* x     = (const float*)d_in[0];
    const float* gamma = (const float*)d_in[1];
    const float* beta  = (const float*)d_in[2];
    const float* wq    = (const float*)d_in[3];
    const float* bq    = (const float*)d_in[4];
    const float* wk    = (const float*)d_in[5];
    const float* bk    = (const float*)d_in[6];
    const float* wv    = (const float*)d_in[7];
    const float* bv    = (const float*)d_in[8];
    const float* wo    = (const float*)d_in[9];
    const float* bo    = (const float*)d_in[10];
    float* out = (float*)d_out;

    bf16 *ph, *pqkv, *ps, *pw, *pvpt;
    cudaGetSymbolAddress((void**)&ph, g_h);
    cudaGetSymbolAddress((void**)&pqkv, g_qkv);
    cudaGetSymbolAddress((void**)&ps, g_s);
    cudaGetSymbolAddress((void**)&pw, g_w);
    cudaGetSymbolAddress((void**)&pvpt, g_vpt);

    cudaFuncSetAttribute(tgemm_kernel<2>, cudaFuncAttributeMaxDynamicSharedMemorySize, SMEM_BYTES);
    cudaFuncSetAttribute(tgemm_kernel<4>, cudaFuncAttributeMaxDynamicSharedMemorySize, SMEM_BYTES);
    cudaFuncSetAttribute(tgemm_kernel<5>, cudaFuncAttributeMaxDynamicSharedMemorySize, SMEM_BYTES);
    cudaFuncSetAttribute(tgemm_kernel<7>, cudaFuncAttributeMaxDynamicSharedMemorySize, SMEM_BYTES);

    // 0) prep: weights->bf16, biases, GN stats (single launch)
    prep_kernel<<<1030 + BB * GG, 256>>>(wq, wk, wv, wo, bq, bk, bv, x);

    // 1) normalize + transpose
    gn_norm_t_kernel<<<dim3(HWN / 32, CC / 32, BB), dim3(32, 8)>>>(x, gamma, beta);

    const int Mflat = BB * HWN;

    // 2) fused QKV projection: [32768, 1536] = h @ [wq|wk|wv]^T (all row-major)
    dim3 gqkv(3 * CC / BN, Mflat / BM, 1);  // (12, 256)
    tgemm_kernel<4><<<gqkv, 256, SMEM_BYTES>>>(ph, pw, nullptr, nullptr, nullptr,
        CC, CC, 0, 0, 0, 0, CC / KC, 1.f);

    // 3) scores + exp + row-sum partials: P = exp(alpha * Q K^T)
    dim3 gscore(HWN / BN, HWN / BM, BB);    // (32, 32, 8)
    tgemm_kernel<5><<<gscore, 256, SMEM_BYTES>>>(
        pqkv, pqkv + REG_SZ, nullptr, nullptr, ps,
        CC, CC, HWN,
        (size_t)HWN * CC, (size_t)HWN * CC, (size_t)HWN * HWN,
        CC / KC, ALPHA_LOG2E);

    // 4) V' = V @ Wo^T, transposed store -> g_vpt[b][c][n]
    dim3 gvp(CC / BN, Mflat / BM, 1);       // (4, 256)
    tgemm_kernel<2><<<gvp, 256, SMEM_BYTES>>>(
        pqkv + 2 * (size_t)REG_SZ, pw + 3 * CC * CC, nullptr, nullptr, nullptr,
        CC, CC, 0, 0, 0, 0, CC / KC, 1.f);

    // 5) out = (P @ V') * rinv + bo + resid, transposed f32 -> [b][c][hw]
    dim3 gsv(CC / BN, HWN / BM, BB);        // (4, 32, 8)
    tgemm_kernel<7><<<gsv, 256, SMEM_BYTES>>>(
        ps, pvpt, bo, x, out,
        HWN, HWN, CC,
        (size_t)HWN * HWN, (size_t)CC * HWN, 0,
        HWN / KC, 1.f);
}